// round 12
// baseline (speedup 1.0000x reference)
#include <cuda_runtime.h>
#include <cuda_bf16.h>
#include <cstdint>
#include <math.h>

#define EPSN 1e-6f
#define NB 8
#define NM 16384
#define GRIP_OFF (NB*NM*6)
#define AC_OFF   (GRIP_OFF+16)
#define ROWB 384                 // bytes per smem image row (192 bf16 slots)
#define IMG  49152               // bytes per image (128 rows)

__device__ __align__(16) __nv_bfloat16 g_Whi[5][16384];   // [o][k] row-major 128x128
__device__ __align__(16) __nv_bfloat16 g_Wlo[5][16384];
__device__ float g_bias1[NB*128*3];
__device__ float g_s2v1[NB*128];
__device__ float g_zposn[NB*2*3];
__device__ float g_grip[NB*2];
__device__ int   g_closest[NB*2];

// activation image column layout: n' = (p>>3)*24 + d*8 + (p&7)
// chunk(16B) index = (p>>3)*3 + d ; warp wq owns chunks wq*6..wq*6+5 (2 pblocks x 3 d)

// ---------------- helpers ----------------
__device__ __forceinline__ uint32_t smem_u32(const void* p){
    uint32_t a; asm("{ .reg .u64 t; cvta.to.shared.u64 t, %1; cvt.u32.u64 %0, t; }" : "=r"(a) : "l"(p)); return a;
}
__device__ __forceinline__ uint32_t pk_bf(float a, float b){
    return (uint32_t)__bfloat16_as_ushort(__float2bfloat16(a)) |
           ((uint32_t)__bfloat16_as_ushort(__float2bfloat16(b)) << 16);
}
__device__ __forceinline__ float bl(uint32_t v){ return __bfloat162float(__ushort_as_bfloat16((unsigned short)(v & 0xFFFF))); }
__device__ __forceinline__ float bhf(uint32_t v){ return __bfloat162float(__ushort_as_bfloat16((unsigned short)(v >> 16))); }

__device__ __forceinline__ void mma_bf16(float* c, const uint32_t* a, uint32_t b0, uint32_t b1){
    asm("mma.sync.aligned.m16n8k16.row.col.f32.bf16.bf16.f32 "
        "{%0,%1,%2,%3},{%4,%5,%6,%7},{%8,%9},{%0,%1,%2,%3};"
        : "+f"(c[0]), "+f"(c[1]), "+f"(c[2]), "+f"(c[3])
        : "r"(a[0]), "r"(a[1]), "r"(a[2]), "r"(a[3]), "r"(b0), "r"(b1));
}
__device__ __forceinline__ void ldsm4t(uint32_t& r0, uint32_t& r1, uint32_t& r2, uint32_t& r3, uint32_t addr){
    asm volatile("ldmatrix.sync.aligned.m8n8.x4.trans.shared.b16 {%0,%1,%2,%3}, [%4];"
        : "=r"(r0), "=r"(r1), "=r"(r2), "=r"(r3) : "r"(addr) : "memory");
}

// one GEMM layer: NAT A-tiles (16 rows each) x 6 n8-tiles, fused 3-term compensation
template<int NAT>
__device__ __forceinline__ void layer_fused(float acc[NAT][6][4],
    const __nv_bfloat16* Whi, const __nv_bfloat16* Wlo,
    uint32_t sbH, uint32_t sbL, int wq, int mrow0,
    int qr, int rB, int chL, int key)
{
    #pragma unroll
    for (int at = 0; at < NAT; at++)
        #pragma unroll
        for (int j = 0; j < 6; j++){ acc[at][j][0]=0.f; acc[at][j][1]=0.f; acc[at][j][2]=0.f; acc[at][j][3]=0.f; }

    const int ca = (rB & 3)*2;
    const uint32_t rowH = sbH + (uint32_t)rB*ROWB;
    const uint32_t rowL = sbL + (uint32_t)rB*ROWB;

    #pragma unroll
    for (int kt = 0; kt < 8; kt++){
        uint32_t afh[NAT][4], afl[NAT][4];
        #pragma unroll
        for (int at = 0; at < NAT; at++){
            const __nv_bfloat16* ph = Whi + (mrow0 + at*16 + qr)*128 + ca + kt*16;
            const __nv_bfloat16* pl = Wlo + (mrow0 + at*16 + qr)*128 + ca + kt*16;
            afh[at][0] = *(const uint32_t*)(ph);        afl[at][0] = *(const uint32_t*)(pl);
            afh[at][1] = *(const uint32_t*)(ph + 1024); afl[at][1] = *(const uint32_t*)(pl + 1024);
            afh[at][2] = *(const uint32_t*)(ph + 8);    afl[at][2] = *(const uint32_t*)(pl + 8);
            afh[at][3] = *(const uint32_t*)(ph + 1032); afl[at][3] = *(const uint32_t*)(pl + 1032);
        }
        const uint32_t kb = (uint32_t)kt*16*ROWB;
        #pragma unroll
        for (int u = 0; u < 3; u++){
            const uint32_t coff = (uint32_t)((wq*6 + 2*u + chL) ^ key) << 4;
            uint32_t h0,h1,h2,h3, l0,l1,l2,l3;
            ldsm4t(h0,h1,h2,h3, rowH + kb + coff);
            ldsm4t(l0,l1,l2,l3, rowL + kb + coff);
            #pragma unroll
            for (int at = 0; at < NAT; at++){
                mma_bf16(acc[at][2*u],   afh[at], h0, h1);   // hi*hi
                mma_bf16(acc[at][2*u+1], afh[at], h2, h3);
                mma_bf16(acc[at][2*u],   afh[at], l0, l1);   // hi_W * lo_X
                mma_bf16(acc[at][2*u+1], afh[at], l2, l3);
                mma_bf16(acc[at][2*u],   afl[at], h0, h1);   // lo_W * hi_X
                mma_bf16(acc[at][2*u+1], afl[at], h2, h3);
            }
        }
    }
}

// epilogues: MODE 0 = bias+gate, 1 = LNA, 2 = raw copy. Writes split h back to images.
template<int MODE>
__device__ __forceinline__ void epi(float acc[2][6][4], char* sm, int wq, int mrow0,
                                    int qr, int cb, int bbase)
{
    #pragma unroll
    for (int at = 0; at < 2; at++){
        #pragma unroll
        for (int r = 0; r < 2; r++){
            const int o = mrow0 + at*16 + qr + r*8;
            const int keyo = o & 7;
            float b0=0.f, b1=0.f, b2=0.f, sv=0.f;
            if (MODE == 0){
                b0 = g_bias1[(bbase+o)*3+0]; b1 = g_bias1[(bbase+o)*3+1]; b2 = g_bias1[(bbase+o)*3+2];
                sv = g_s2v1[bbase+o];
            }
            #pragma unroll
            for (int pbL = 0; pbL < 2; pbL++){
                uint32_t offd[3];
                #pragma unroll
                for (int d = 0; d < 3; d++){
                    int chunk = wq*6 + pbL*3 + d;
                    offd[d] = (uint32_t)(o*ROWB + ((chunk ^ keyo) << 4) + cb*2);
                }
                float x0 = acc[at][pbL*3+0][2*r], x1 = acc[at][pbL*3+0][2*r+1];
                float y0 = acc[at][pbL*3+1][2*r], y1 = acc[at][pbL*3+1][2*r+1];
                float z0 = acc[at][pbL*3+2][2*r], z1 = acc[at][pbL*3+2][2*r+1];
                float h3[3][2];
                if (MODE == 0){
                    float q00=x0+b0, q10=y0+b1, q20=z0+b2;
                    float q01=x1+b0, q11=y1+b1, q21=z1+b2;
                    float g0 = 1.0f + sv/(sqrtf(q00*q00+q10*q10+q20*q20)+EPSN);
                    float g1 = 1.0f + sv/(sqrtf(q01*q01+q11*q11+q21*q21)+EPSN);
                    h3[0][0]=q00*g0; h3[1][0]=q10*g0; h3[2][0]=q20*g0;
                    h3[0][1]=q01*g1; h3[1][1]=q11*g1; h3[2][1]=q21*g1;
                } else if (MODE == 2){
                    h3[0][0]=x0; h3[0][1]=x1; h3[1][0]=y0; h3[1][1]=y1; h3[2][0]=z0; h3[2][1]=z1;
                } else {
                    float q[3][2];
                    #pragma unroll
                    for (int d = 0; d < 3; d++){
                        uint32_t qh = *(uint32_t*)(sm + offd[d]);
                        uint32_t ql = *(uint32_t*)(sm + IMG + offd[d]);
                        q[d][0] = bl(qh)+bl(ql); q[d][1] = bhf(qh)+bhf(ql);
                    }
                    float inv0 = 1.0f/(sqrtf(x0*x0+y0*y0+z0*z0)+EPSN);
                    float mf0  = fminf((q[0][0]*x0+q[1][0]*y0+q[2][0]*z0)*inv0, 0.0f)*inv0;
                    float inv1 = 1.0f/(sqrtf(x1*x1+y1*y1+z1*z1)+EPSN);
                    float mf1  = fminf((q[0][1]*x1+q[1][1]*y1+q[2][1]*z1)*inv1, 0.0f)*inv1;
                    h3[0][0]=q[0][0]-mf0*x0; h3[1][0]=q[1][0]-mf0*y0; h3[2][0]=q[2][0]-mf0*z0;
                    h3[0][1]=q[0][1]-mf1*x1; h3[1][1]=q[1][1]-mf1*y1; h3[2][1]=q[2][1]-mf1*z1;
                }
                #pragma unroll
                for (int d = 0; d < 3; d++){
                    uint32_t hw = pk_bf(h3[d][0], h3[d][1]);
                    uint32_t lw = pk_bf(h3[d][0]-bl(hw), h3[d][1]-bhf(hw));
                    *(uint32_t*)(sm + offd[d])       = hw;
                    *(uint32_t*)(sm + IMG + offd[d]) = lw;
                }
            }
        }
    }
}

// ---------------- main kernel ----------------
__global__ void __launch_bounds__(512, 1)
main_mma(const float* __restrict__ pf, const float* __restrict__ scale,
         const float* __restrict__ center, float* __restrict__ out)
{
    extern __shared__ char sm[];
    const uint32_t sbH = smem_u32(sm), sbL = sbH + IMG;
    const int tid = threadIdx.x, w = tid >> 5, lane = tid & 31;
    const int b = blockIdx.y, m0 = blockIdx.x * 64;
    const int wq = w & 3, wm = w >> 2;           // n-quarter / M-group
    const int qr = lane >> 2, cb = (lane & 3)*2;
    const int rB = lane & 15, chL = lane >> 4, key = rB & 7;

    // build hi/lo activation images: row = channel c, col n' = (p>>3)*24 + d*8 + (p&7)
    #pragma unroll 1
    for (int it = 0; it < 12; it++){
        int idx = tid + it*512;
        int seg = idx & 15, d = (idx >> 4) % 3, c = idx / 48;
        float4 v = __ldg((const float4*)(pf + (((size_t)(b*128+c)*3+d)*NM + m0 + seg*4)));
        int pb = seg >> 1, pl0 = (seg & 1)*4;
        int chunk = pb*3 + d;
        uint32_t off = (uint32_t)(c*ROWB + ((chunk ^ (c&7)) << 4) + pl0*2);
        uint2 hv = make_uint2(pk_bf(v.x, v.y), pk_bf(v.z, v.w));
        uint2 lv = make_uint2(pk_bf(v.x - bl(hv.x), v.y - bhf(hv.x)),
                              pk_bf(v.z - bl(hv.y), v.w - bhf(hv.y)));
        *(uint2*)(sm + off)       = hv;
        *(uint2*)(sm + IMG + off) = lv;
    }
    __syncthreads();

    float acc[2][6][4];
    const int mrow0 = wm*32;
    const int bbase = b*128;

    layer_fused<2>(acc, g_Whi[0], g_Wlo[0], sbH, sbL, wq, mrow0, qr, rB, chL, key);
    __syncthreads();
    epi<0>(acc, sm, wq, mrow0, qr, cb, bbase);
    __syncthreads();

    layer_fused<2>(acc, g_Whi[1], g_Wlo[1], sbH, sbL, wq, mrow0, qr, rB, chL, key);
    __syncthreads();
    epi<1>(acc, sm, wq, mrow0, qr, cb, bbase);
    __syncthreads();

    layer_fused<2>(acc, g_Whi[2], g_Wlo[2], sbH, sbL, wq, mrow0, qr, rB, chL, key);
    __syncthreads();
    epi<2>(acc, sm, wq, mrow0, qr, cb, bbase);
    __syncthreads();

    layer_fused<2>(acc, g_Whi[3], g_Wlo[3], sbH, sbL, wq, mrow0, qr, rB, chL, key);
    __syncthreads();
    epi<1>(acc, sm, wq, mrow0, qr, cb, bbase);
    __syncthreads();

    // final projection: only rows 0-1 valid; wm==0 warps, single A-tile
    if (wm == 0){
        float facc[1][6][4];
        layer_fused<1>(facc, g_Whi[4], g_Wlo[4], sbH, sbL, wq, 0, qr, rB, chL, key);
        if (lane < 8){
            const float sc = __ldg(scale + b);
            const int o2 = qr;   // 0 or 1
            #pragma unroll
            for (int pbL = 0; pbL < 2; pbL++){
                #pragma unroll
                for (int d = 0; d < 3; d++){
                    #pragma unroll
                    for (int j = 0; j < 2; j++){
                        int p = (wq*2 + pbL)*8 + cb + j;
                        float v = facc[0][pbL*3+d][j];
                        if (o2 == 0) v = v*sc + __ldg(center + b*3 + d);
                        out[((size_t)b*NM + m0 + p)*6 + o2*3 + d] = v;
                    }
                }
            }
        }
    }
}

// ---------------- weight split images ----------------
__global__ void buildW_k(const float* __restrict__ W1x, const float* __restrict__ W1xd,
                         const float* __restrict__ W2x, const float* __restrict__ W2xd,
                         const float* __restrict__ W3x)
{
    const int m = blockIdx.x;
    for (int i = threadIdx.x; i < 16384; i += 256){
        int o = i >> 7, k = i & 127;
        float w = (m==0) ? W1x[o*136+k] : (m==1) ? W1xd[o*128+k] : (m==2) ? W2x[o*128+k]
                : (m==3) ? W2xd[o*128+k] : ((o<2) ? W3x[o*128+k] : 0.0f);
        __nv_bfloat16 h = __float2bfloat16(w);
        g_Whi[m][i] = h;
        g_Wlo[m][i] = __float2bfloat16(w - __bfloat162float(h));
    }
}

// ---------------- prep: bias/s2v + gripper branch (fp32) ----------------
__global__ void prep_k(const float* __restrict__ z_pos, const float* __restrict__ z_dir,
                       const float* __restrict__ z_scalar, const float* __restrict__ gfeat,
                       const float* __restrict__ center, const float* __restrict__ scale,
                       const float* __restrict__ W1x, const float* __restrict__ W1x_s,
                       const float* __restrict__ W1g, const float* __restrict__ W1g_d,
                       const float* __restrict__ W1g_s, const float* __restrict__ W2g,
                       const float* __restrict__ W2g_d, const float* __restrict__ Wg_vs,
                       float* __restrict__ out)
{
    __shared__ float vg[136*3], bq[128*3], bhm[128*3], nh[128], zs[8*3];
    const int b = blockIdx.x, o = threadIdx.x;
    if (o < 24){
        int r = o/3, d = o%3;
        float v = (r < 2) ? (z_pos[(b*2+r)*3+d] - center[b*3+d]) / scale[b] : z_dir[(b*6+(r-2))*3+d];
        zs[r*3+d] = v;
        if (r < 2) g_zposn[(b*2+r)*3+d] = v;
    }
    __syncthreads();
    {
        g_s2v1[b*128+o] = W1x_s[o*2]*z_scalar[b*2] + W1x_s[o*2+1]*z_scalar[b*2+1];
        #pragma unroll
        for (int d = 0; d < 3; d++){
            float s = 0.0f;
            #pragma unroll
            for (int k = 0; k < 8; k++) s += W1x[o*136 + 128 + k] * zs[k*3+d];
            g_bias1[(b*128+o)*3+d] = s;
        }
    }
    for (int i = o; i < 408; i += 128){
        int c = i/3, d = i%3;
        vg[i] = (c < 128) ? gfeat[(b*128+c)*3+d] : zs[(c-128)*3+d];
    }
    __syncthreads();
    float q[3], dv[3];
    #pragma unroll
    for (int d = 0; d < 3; d++){ float s=0; for (int c=0;c<136;c++) s += W1g[o*136+c]*vg[c*3+d]; q[d]=s; }
    {
        float sg = W1g_s[o*2]*z_scalar[b*2] + W1g_s[o*2+1]*z_scalar[b*2+1];
        float g = 1.0f + sg/(sqrtf(q[0]*q[0]+q[1]*q[1]+q[2]*q[2])+EPSN);
        q[0]*=g; q[1]*=g; q[2]*=g;
    }
    bq[o*3]=q[0]; bq[o*3+1]=q[1]; bq[o*3+2]=q[2];
    __syncthreads();
    #pragma unroll
    for (int d = 0; d < 3; d++){ float s=0; for (int c=0;c<128;c++) s += W1g_d[o*128+c]*bq[c*3+d]; dv[d]=s; }
    {
        float inv = 1.0f/(sqrtf(dv[0]*dv[0]+dv[1]*dv[1]+dv[2]*dv[2]) + EPSN);
        float mf = fminf((q[0]*dv[0]+q[1]*dv[1]+q[2]*dv[2])*inv, 0.0f)*inv;
        q[0]-=mf*dv[0]; q[1]-=mf*dv[1]; q[2]-=mf*dv[2];
    }
    bhm[o*3]=q[0]; bhm[o*3+1]=q[1]; bhm[o*3+2]=q[2];
    __syncthreads();
    #pragma unroll
    for (int d = 0; d < 3; d++){ float s=0; for (int c=0;c<128;c++) s += W2g[o*128+c]*bhm[c*3+d]; q[d]=s; }
    bq[o*3]=q[0]; bq[o*3+1]=q[1]; bq[o*3+2]=q[2];
    __syncthreads();
    #pragma unroll
    for (int d = 0; d < 3; d++){ float s=0; for (int c=0;c<128;c++) s += W2g_d[o*128+c]*bq[c*3+d]; dv[d]=s; }
    {
        float inv = 1.0f/(sqrtf(dv[0]*dv[0]+dv[1]*dv[1]+dv[2]*dv[2]) + EPSN);
        float mf = fminf((q[0]*dv[0]+q[1]*dv[1]+q[2]*dv[2])*inv, 0.0f)*inv;
        q[0]-=mf*dv[0]; q[1]-=mf*dv[1]; q[2]-=mf*dv[2];
    }
    nh[o] = sqrtf(q[0]*q[0]+q[1]*q[1]+q[2]*q[2]);
    __syncthreads();
    if (o < 2){
        float s = 0; for (int c = 0; c < 128; c++) s += Wg_vs[o*128+c]*nh[c];
        float gr = 1.0f/(1.0f+expf(-s));
        g_grip[b*2+o] = gr;
        out[GRIP_OFF + b*2+o] = gr;
    }
}

__global__ void argmin_k(const float* __restrict__ pc)
{
    __shared__ float sv[256]; __shared__ int si[256];
    const int be = blockIdx.x, b = be >> 1;
    const float zx = g_zposn[be*3], zy = g_zposn[be*3+1], zz = g_zposn[be*3+2];
    const float* p = pc + (size_t)b*NM*3;
    float best = 3.4e38f; int bi = 0;
    for (int m = threadIdx.x; m < NM; m += blockDim.x){
        float dx=zx-p[m*3], dy=zy-p[m*3+1], dz=zz-p[m*3+2];
        float d = sqrtf(dx*dx+dy*dy+dz*dz);
        if (d < best){ best = d; bi = m; }
    }
    sv[threadIdx.x]=best; si[threadIdx.x]=bi;
    __syncthreads();
    for (int s = 128; s > 0; s >>= 1){
        if (threadIdx.x < s){
            float ov = sv[threadIdx.x+s]; int oi = si[threadIdx.x+s];
            if (ov < sv[threadIdx.x] || (ov == sv[threadIdx.x] && oi < si[threadIdx.x])){
                sv[threadIdx.x]=ov; si[threadIdx.x]=oi;
            }
        }
        __syncthreads();
    }
    if (threadIdx.x == 0) g_closest[be] = si[0];
}

__global__ void assemble_k(float* __restrict__ out)
{
    const int t = threadIdx.x;
    if (t < 112){
        int b = t/14, j = t%14, e = j/7, r = j%7;
        float v;
        if (r == 0) v = g_grip[b*2+e];
        else { int m = g_closest[b*2+e]; v = out[((size_t)b*NM+m)*6 + (r-1)]; }
        out[AC_OFF + t] = v;
    }
}

// ---------------- launch ----------------
extern "C" void kernel_launch(void* const* d_in, const int* in_sizes, int n_in,
                              void* d_out, int out_size)
{
    const float* pc        = (const float*)d_in[0];
    const float* z_pos     = (const float*)d_in[1];
    const float* z_dir     = (const float*)d_in[2];
    const float* z_scalar  = (const float*)d_in[3];
    const float* point_feat= (const float*)d_in[4];
    const float* gfeat     = (const float*)d_in[5];
    const float* center    = (const float*)d_in[6];
    const float* scale     = (const float*)d_in[7];
    const float* W1x       = (const float*)d_in[8];
    const float* W1x_d     = (const float*)d_in[9];
    const float* W1x_s     = (const float*)d_in[10];
    const float* W2x       = (const float*)d_in[11];
    const float* W2x_d     = (const float*)d_in[12];
    const float* W3x       = (const float*)d_in[13];
    const float* W1g       = (const float*)d_in[14];
    const float* W1g_d     = (const float*)d_in[15];
    const float* W1g_s     = (const float*)d_in[16];
    const float* W2g       = (const float*)d_in[17];
    const float* W2g_d     = (const float*)d_in[18];
    const float* Wg_vs     = (const float*)d_in[19];
    float* out = (float*)d_out;

    cudaFuncSetAttribute(main_mma, cudaFuncAttributeMaxDynamicSharedMemorySize, 2*IMG);

    buildW_k<<<5, 256>>>(W1x, W1x_d, W2x, W2x_d, W3x);
    prep_k<<<NB, 128>>>(z_pos, z_dir, z_scalar, gfeat, center, scale,
                        W1x, W1x_s, W1g, W1g_d, W1g_s, W2g, W2g_d, Wg_vs, out);
    argmin_k<<<16, 256>>>(pc);
    main_mma<<<dim3(NM/64, NB), 512, 2*IMG>>>(point_feat, scale, center, out);
    assemble_k<<<1, 128>>>(out);
}

// round 13
// speedup vs baseline: 1.3788x; 1.3788x over previous
#include <cuda_runtime.h>
#include <cuda_bf16.h>
#include <cstdint>
#include <math.h>

#define EPSN 1e-6f
#define NB 8
#define NM 16384
#define GRIP_OFF (NB*NM*6)
#define AC_OFF   (GRIP_OFF+16)
#define ROWB 384                 // bytes per smem image row (192 bf16 slots)
#define IMG  49152               // bytes per image (128 rows)
#define WOFF_H 98304             // weight stage hi (32KB)
#define WOFF_L 131072            // weight stage lo (32KB)
#define SMEM_TOTAL 163840

__device__ __align__(16) __nv_bfloat16 g_Whi[5][16384];   // [o][k] row-major 128x128
__device__ __align__(16) __nv_bfloat16 g_Wlo[5][16384];
__device__ float g_bias1[NB*128*3];
__device__ float g_s2v1[NB*128];
__device__ float g_zposn[NB*2*3];
__device__ float g_grip[NB*2];
__device__ int   g_closest[NB*2];

// ---------------- helpers ----------------
__device__ __forceinline__ uint32_t smem_u32(const void* p){
    uint32_t a; asm("{ .reg .u64 t; cvta.to.shared.u64 t, %1; cvt.u32.u64 %0, t; }" : "=r"(a) : "l"(p)); return a;
}
__device__ __forceinline__ uint32_t pk_bf(float a, float b){
    return (uint32_t)__bfloat16_as_ushort(__float2bfloat16(a)) |
           ((uint32_t)__bfloat16_as_ushort(__float2bfloat16(b)) << 16);
}
__device__ __forceinline__ float bl(uint32_t v){ return __bfloat162float(__ushort_as_bfloat16((unsigned short)(v & 0xFFFF))); }
__device__ __forceinline__ float bhf(uint32_t v){ return __bfloat162float(__ushort_as_bfloat16((unsigned short)(v >> 16))); }

__device__ __forceinline__ void mma_bf16(float* c, const uint32_t* a, uint32_t b0, uint32_t b1){
    asm("mma.sync.aligned.m16n8k16.row.col.f32.bf16.bf16.f32 "
        "{%0,%1,%2,%3},{%4,%5,%6,%7},{%8,%9},{%0,%1,%2,%3};"
        : "+f"(c[0]), "+f"(c[1]), "+f"(c[2]), "+f"(c[3])
        : "r"(a[0]), "r"(a[1]), "r"(a[2]), "r"(a[3]), "r"(b0), "r"(b1));
}
__device__ __forceinline__ void ldsm4t(uint32_t& r0, uint32_t& r1, uint32_t& r2, uint32_t& r3, uint32_t addr){
    asm volatile("ldmatrix.sync.aligned.m8n8.x4.trans.shared.b16 {%0,%1,%2,%3}, [%4];"
        : "=r"(r0), "=r"(r1), "=r"(r2), "=r"(r3) : "r"(addr) : "memory");
}
__device__ __forceinline__ void ldsm4(uint32_t* r, uint32_t addr){
    asm volatile("ldmatrix.sync.aligned.m8n8.x4.shared.b16 {%0,%1,%2,%3}, [%4];"
        : "=r"(r[0]), "=r"(r[1]), "=r"(r[2]), "=r"(r[3]) : "r"(addr) : "memory");
}
__device__ __forceinline__ void cp16(void* dst, const void* src){
    unsigned d = smem_u32(dst);
    asm volatile("cp.async.cg.shared.global [%0], [%1], 16;" :: "r"(d), "l"(src));
}
__device__ __forceinline__ void cpcommit(){ asm volatile("cp.async.commit_group;"); }
__device__ __forceinline__ void cpwait0(){ asm volatile("cp.async.wait_group 0;"); }

// one GEMM layer: 16 o-rows x 12 n8-tiles, fused 3-term compensation, W from smem
__device__ __forceinline__ void layer_fused12(float acc[12][4],
    uint32_t WHs, uint32_t WLs, uint32_t sbH, uint32_t sbL,
    int h, int mrow0, int lane, int rB, int chL, int key)
{
    #pragma unroll
    for (int i = 0; i < 12; i++){ acc[i][0]=0.f; acc[i][1]=0.f; acc[i][2]=0.f; acc[i][3]=0.f; }

    const int rowA = mrow0 + (lane & 15);
    const uint32_t abase = (uint32_t)rowA * 256;
    const int keyA = lane & 7;
    const uint32_t rowH = sbH + (uint32_t)rB*ROWB;
    const uint32_t rowL = sbL + (uint32_t)rB*ROWB;

    #pragma unroll
    for (int kt = 0; kt < 8; kt++){
        const uint32_t ka = (uint32_t)(((2*kt + chL) ^ keyA) << 4);
        uint32_t aH[4], aL[4];
        ldsm4(aH, WHs + abase + ka);
        ldsm4(aL, WLs + abase + ka);
        const uint32_t kb = (uint32_t)kt*16*ROWB;
        #pragma unroll
        for (int d = 0; d < 3; d++){
            #pragma unroll
            for (int u = 0; u < 2; u++){
                int chunk = d*8 + h*4 + 2*u + chL;
                uint32_t addr = kb + ((uint32_t)(chunk ^ key) << 4);
                uint32_t b0,b1,b2,b3, l0,l1,l2,l3;
                ldsm4t(b0,b1,b2,b3, rowH + addr);
                ldsm4t(l0,l1,l2,l3, rowL + addr);
                const int j = d*4 + 2*u;
                mma_bf16(acc[j],   aH, b0, b1);
                mma_bf16(acc[j+1], aH, b2, b3);
                mma_bf16(acc[j],   aH, l0, l1);
                mma_bf16(acc[j+1], aH, l2, l3);
                mma_bf16(acc[j],   aL, b0, b1);
                mma_bf16(acc[j+1], aL, b2, b3);
            }
        }
    }
}

// epilogues: MODE 0 = bias+gate, 1 = LNA, 2 = raw copy. Writes split h back to images.
template<int MODE>
__device__ __forceinline__ void epi(float acc[12][4], char* sm, int o0, int h, int cb, int bbase)
{
    #pragma unroll
    for (int r = 0; r < 2; r++){
        const int o = o0 + r*8;
        const int keyo = o & 7;
        float b0=0.f, b1=0.f, b2=0.f, sv=0.f;
        if (MODE == 0){
            b0 = g_bias1[(bbase+o)*3+0]; b1 = g_bias1[(bbase+o)*3+1]; b2 = g_bias1[(bbase+o)*3+2];
            sv = g_s2v1[bbase+o];
        }
        #pragma unroll
        for (int lp = 0; lp < 4; lp++){
            const int pt = h*4 + lp;
            uint32_t offd[3];
            #pragma unroll
            for (int d = 0; d < 3; d++)
                offd[d] = (uint32_t)(o*ROWB + (((d*8+pt) ^ keyo) << 4) + cb*2);
            float x0 = acc[lp][2*r],    x1 = acc[lp][2*r+1];
            float y0 = acc[4+lp][2*r],  y1 = acc[4+lp][2*r+1];
            float z0 = acc[8+lp][2*r],  z1 = acc[8+lp][2*r+1];
            float h3[3][2];
            if (MODE == 0){
                float q00=x0+b0, q10=y0+b1, q20=z0+b2;
                float q01=x1+b0, q11=y1+b1, q21=z1+b2;
                float g0 = 1.0f + sv/(sqrtf(q00*q00+q10*q10+q20*q20)+EPSN);
                float g1 = 1.0f + sv/(sqrtf(q01*q01+q11*q11+q21*q21)+EPSN);
                h3[0][0]=q00*g0; h3[1][0]=q10*g0; h3[2][0]=q20*g0;
                h3[0][1]=q01*g1; h3[1][1]=q11*g1; h3[2][1]=q21*g1;
            } else if (MODE == 2){
                h3[0][0]=x0; h3[0][1]=x1; h3[1][0]=y0; h3[1][1]=y1; h3[2][0]=z0; h3[2][1]=z1;
            } else {
                float q[3][2];
                #pragma unroll
                for (int d = 0; d < 3; d++){
                    uint32_t qh = *(uint32_t*)(sm + offd[d]);
                    uint32_t ql = *(uint32_t*)(sm + IMG + offd[d]);
                    q[d][0] = bl(qh)+bl(ql); q[d][1] = bhf(qh)+bhf(ql);
                }
                float inv0 = 1.0f/(sqrtf(x0*x0+y0*y0+z0*z0)+EPSN);
                float mf0  = fminf((q[0][0]*x0+q[1][0]*y0+q[2][0]*z0)*inv0, 0.0f)*inv0;
                float inv1 = 1.0f/(sqrtf(x1*x1+y1*y1+z1*z1)+EPSN);
                float mf1  = fminf((q[0][1]*x1+q[1][1]*y1+q[2][1]*z1)*inv1, 0.0f)*inv1;
                h3[0][0]=q[0][0]-mf0*x0; h3[1][0]=q[1][0]-mf0*y0; h3[2][0]=q[2][0]-mf0*z0;
                h3[0][1]=q[0][1]-mf1*x1; h3[1][1]=q[1][1]-mf1*y1; h3[2][1]=q[2][1]-mf1*z1;
            }
            #pragma unroll
            for (int d = 0; d < 3; d++){
                uint32_t hw = pk_bf(h3[d][0], h3[d][1]);
                uint32_t lw = pk_bf(h3[d][0]-bl(hw), h3[d][1]-bhf(hw));
                *(uint32_t*)(sm + offd[d])       = hw;
                *(uint32_t*)(sm + IMG + offd[d]) = lw;
            }
        }
    }
}

// ---------------- main kernel ----------------
__global__ void __launch_bounds__(512, 1)
main_mma(const float* __restrict__ pf, const float* __restrict__ scale,
         const float* __restrict__ center, float* __restrict__ out)
{
    extern __shared__ char sm[];
    const uint32_t sb = smem_u32(sm);
    const uint32_t sbH = sb, sbL = sb + IMG;
    const uint32_t WHs = sb + WOFF_H, WLs = sb + WOFF_L;
    const int tid = threadIdx.x, w = tid >> 5, lane = tid & 31;
    const int b = blockIdx.y, m0 = blockIdx.x * 64;
    const int og = w >> 1, h = w & 1;
    const int qr = lane >> 2, cb = (lane & 3)*2;
    const int rB = lane & 15, chL = lane >> 4, key = rB & 7;

    // stage layer-0 weights into smem (swizzled): chunk i -> o=i>>4, kc=i&15
    {
        const char* srcH = (const char*)g_Whi[0];
        const char* srcL = (const char*)g_Wlo[0];
        #pragma unroll
        for (int t = 0; t < 4; t++){
            int i = tid + t*512;
            int o = i >> 4, kc = i & 15;
            uint32_t dst = (uint32_t)(o*256 + ((kc ^ (o&7)) << 4));
            cp16(sm + WOFF_H + dst, srcH + (size_t)i*16);
            cp16(sm + WOFF_L + dst, srcL + (size_t)i*16);
        }
        cpcommit();
    }

    // build hi/lo activation images: row = channel c, col n = d*64+p
    #pragma unroll 1
    for (int it = 0; it < 12; it++){
        int idx = tid + it*512;
        int seg = idx & 15, d = (idx >> 4) % 3, c = idx / 48;
        float4 v = __ldg((const float4*)(pf + (((size_t)(b*128+c)*3+d)*NM + m0 + seg*4)));
        int n0 = d*64 + seg*4;
        uint32_t off = (uint32_t)(c*ROWB + (((n0>>3) ^ (c&7)) << 4) + (n0&7)*2);
        uint32_t h01 = pk_bf(v.x, v.y), h23 = pk_bf(v.z, v.w);
        uint32_t l01 = pk_bf(v.x - bl(h01), v.y - bhf(h01));
        uint32_t l23 = pk_bf(v.z - bl(h23), v.w - bhf(h23));
        *(uint32_t*)(sm + off)           = h01;
        *(uint32_t*)(sm + off + 4)       = h23;
        *(uint32_t*)(sm + IMG + off)     = l01;
        *(uint32_t*)(sm + IMG + off + 4) = l23;
    }
    cpwait0();
    __syncthreads();

    float acc[12][4];
    const int o0 = og*16 + qr;
    const int bbase = b*128;

    #pragma unroll 1
    for (int l = 0; l < 4; l++){
        layer_fused12(acc, WHs, WLs, sbH, sbL, h, og*16, lane, rB, chL, key);
        __syncthreads();
        // prefetch next layer's weights during epilogue
        {
            const char* srcH = (const char*)g_Whi[l+1];
            const char* srcL = (const char*)g_Wlo[l+1];
            #pragma unroll
            for (int t = 0; t < 4; t++){
                int i = tid + t*512;
                int o = i >> 4, kc = i & 15;
                uint32_t dst = (uint32_t)(o*256 + ((kc ^ (o&7)) << 4));
                cp16(sm + WOFF_H + dst, srcH + (size_t)i*16);
                cp16(sm + WOFF_L + dst, srcL + (size_t)i*16);
            }
            cpcommit();
        }
        if      (l == 0) epi<0>(acc, sm, o0, h, cb, bbase);
        else if (l == 1) epi<1>(acc, sm, o0, h, cb, bbase);
        else if (l == 2) epi<2>(acc, sm, o0, h, cb, bbase);
        else             epi<1>(acc, sm, o0, h, cb, bbase);
        cpwait0();
        __syncthreads();
    }

    // final projection: rows 0-1 of tile 0; only og==0 warps participate
    if (og == 0){
        layer_fused12(acc, WHs, WLs, sbH, sbL, h, 0, lane, rB, chL, key);
        if (lane < 8){
            const float sc = __ldg(scale + b);
            const int o2 = qr;   // 0 or 1
            #pragma unroll
            for (int d = 0; d < 3; d++){
                #pragma unroll
                for (int lp = 0; lp < 4; lp++){
                    const int pt = h*4 + lp;
                    #pragma unroll
                    for (int j = 0; j < 2; j++){
                        int p = pt*8 + cb + j;
                        float v = acc[d*4+lp][j];
                        if (o2 == 0) v = v*sc + __ldg(center + b*3 + d);
                        out[((size_t)b*NM + m0 + p)*6 + o2*3 + d] = v;
                    }
                }
            }
        }
    }
}

// ---------------- weight split images ----------------
__global__ void buildW_k(const float* __restrict__ W1x, const float* __restrict__ W1xd,
                         const float* __restrict__ W2x, const float* __restrict__ W2xd,
                         const float* __restrict__ W3x)
{
    const int m = blockIdx.x;
    for (int i = threadIdx.x; i < 16384; i += 256){
        int o = i >> 7, k = i & 127;
        float w = (m==0) ? W1x[o*136+k] : (m==1) ? W1xd[o*128+k] : (m==2) ? W2x[o*128+k]
                : (m==3) ? W2xd[o*128+k] : ((o<2) ? W3x[o*128+k] : 0.0f);
        __nv_bfloat16 h = __float2bfloat16(w);
        g_Whi[m][i] = h;
        g_Wlo[m][i] = __float2bfloat16(w - __bfloat162float(h));
    }
}

// ---------------- prep: bias/s2v + gripper branch (fp32) ----------------
__global__ void prep_k(const float* __restrict__ z_pos, const float* __restrict__ z_dir,
                       const float* __restrict__ z_scalar, const float* __restrict__ gfeat,
                       const float* __restrict__ center, const float* __restrict__ scale,
                       const float* __restrict__ W1x, const float* __restrict__ W1x_s,
                       const float* __restrict__ W1g, const float* __restrict__ W1g_d,
                       const float* __restrict__ W1g_s, const float* __restrict__ W2g,
                       const float* __restrict__ W2g_d, const float* __restrict__ Wg_vs,
                       float* __restrict__ out)
{
    __shared__ float vg[136*3], bq[128*3], bhm[128*3], nh[128], zs[8*3];
    const int b = blockIdx.x, o = threadIdx.x;
    if (o < 24){
        int r = o/3, d = o%3;
        float v = (r < 2) ? (z_pos[(b*2+r)*3+d] - center[b*3+d]) / scale[b] : z_dir[(b*6+(r-2))*3+d];
        zs[r*3+d] = v;
        if (r < 2) g_zposn[(b*2+r)*3+d] = v;
    }
    __syncthreads();
    {
        g_s2v1[b*128+o] = W1x_s[o*2]*z_scalar[b*2] + W1x_s[o*2+1]*z_scalar[b*2+1];
        #pragma unroll
        for (int d = 0; d < 3; d++){
            float s = 0.0f;
            #pragma unroll
            for (int k = 0; k < 8; k++) s += W1x[o*136 + 128 + k] * zs[k*3+d];
            g_bias1[(b*128+o)*3+d] = s;
        }
    }
    for (int i = o; i < 408; i += 128){
        int c = i/3, d = i%3;
        vg[i] = (c < 128) ? gfeat[(b*128+c)*3+d] : zs[(c-128)*3+d];
    }
    __syncthreads();
    float q[3], dv[3];
    #pragma unroll
    for (int d = 0; d < 3; d++){ float s=0; for (int c=0;c<136;c++) s += W1g[o*136+c]*vg[c*3+d]; q[d]=s; }
    {
        float sg = W1g_s[o*2]*z_scalar[b*2] + W1g_s[o*2+1]*z_scalar[b*2+1];
        float g = 1.0f + sg/(sqrtf(q[0]*q[0]+q[1]*q[1]+q[2]*q[2])+EPSN);
        q[0]*=g; q[1]*=g; q[2]*=g;
    }
    bq[o*3]=q[0]; bq[o*3+1]=q[1]; bq[o*3+2]=q[2];
    __syncthreads();
    #pragma unroll
    for (int d = 0; d < 3; d++){ float s=0; for (int c=0;c<128;c++) s += W1g_d[o*128+c]*bq[c*3+d]; dv[d]=s; }
    {
        float inv = 1.0f/(sqrtf(dv[0]*dv[0]+dv[1]*dv[1]+dv[2]*dv[2]) + EPSN);
        float mf = fminf((q[0]*dv[0]+q[1]*dv[1]+q[2]*dv[2])*inv, 0.0f)*inv;
        q[0]-=mf*dv[0]; q[1]-=mf*dv[1]; q[2]-=mf*dv[2];
    }
    bhm[o*3]=q[0]; bhm[o*3+1]=q[1]; bhm[o*3+2]=q[2];
    __syncthreads();
    #pragma unroll
    for (int d = 0; d < 3; d++){ float s=0; for (int c=0;c<128;c++) s += W2g[o*128+c]*bhm[c*3+d]; q[d]=s; }
    bq[o*3]=q[0]; bq[o*3+1]=q[1]; bq[o*3+2]=q[2];
    __syncthreads();
    #pragma unroll
    for (int d = 0; d < 3; d++){ float s=0; for (int c=0;c<128;c++) s += W2g_d[o*128+c]*bq[c*3+d]; dv[d]=s; }
    {
        float inv = 1.0f/(sqrtf(dv[0]*dv[0]+dv[1]*dv[1]+dv[2]*dv[2]) + EPSN);
        float mf = fminf((q[0]*dv[0]+q[1]*dv[1]+q[2]*dv[2])*inv, 0.0f)*inv;
        q[0]-=mf*dv[0]; q[1]-=mf*dv[1]; q[2]-=mf*dv[2];
    }
    nh[o] = sqrtf(q[0]*q[0]+q[1]*q[1]+q[2]*q[2]);
    __syncthreads();
    if (o < 2){
        float s = 0; for (int c = 0; c < 128; c++) s += Wg_vs[o*128+c]*nh[c];
        float gr = 1.0f/(1.0f+expf(-s));
        g_grip[b*2+o] = gr;
        out[GRIP_OFF + b*2+o] = gr;
    }
}

__global__ void argmin_k(const float* __restrict__ pc)
{
    __shared__ float sv[256]; __shared__ int si[256];
    const int be = blockIdx.x, b = be >> 1;
    const float zx = g_zposn[be*3], zy = g_zposn[be*3+1], zz = g_zposn[be*3+2];
    const float* p = pc + (size_t)b*NM*3;
    float best = 3.4e38f; int bi = 0;
    for (int m = threadIdx.x; m < NM; m += blockDim.x){
        float dx=zx-p[m*3], dy=zy-p[m*3+1], dz=zz-p[m*3+2];
        float d = sqrtf(dx*dx+dy*dy+dz*dz);
        if (d < best){ best = d; bi = m; }
    }
    sv[threadIdx.x]=best; si[threadIdx.x]=bi;
    __syncthreads();
    for (int s = 128; s > 0; s >>= 1){
        if (threadIdx.x < s){
            float ov = sv[threadIdx.x+s]; int oi = si[threadIdx.x+s];
            if (ov < sv[threadIdx.x] || (ov == sv[threadIdx.x] && oi < si[threadIdx.x])){
                sv[threadIdx.x]=ov; si[threadIdx.x]=oi;
            }
        }
        __syncthreads();
    }
    if (threadIdx.x == 0) g_closest[be] = si[0];
}

__global__ void assemble_k(float* __restrict__ out)
{
    const int t = threadIdx.x;
    if (t < 112){
        int b = t/14, j = t%14, e = j/7, r = j%7;
        float v;
        if (r == 0) v = g_grip[b*2+e];
        else { int m = g_closest[b*2+e]; v = out[((size_t)b*NM+m)*6 + (r-1)]; }
        out[AC_OFF + t] = v;
    }
}

// ---------------- launch ----------------
extern "C" void kernel_launch(void* const* d_in, const int* in_sizes, int n_in,
                              void* d_out, int out_size)
{
    const float* pc        = (const float*)d_in[0];
    const float* z_pos     = (const float*)d_in[1];
    const float* z_dir     = (const float*)d_in[2];
    const float* z_scalar  = (const float*)d_in[3];
    const float* point_feat= (const float*)d_in[4];
    const float* gfeat     = (const float*)d_in[5];
    const float* center    = (const float*)d_in[6];
    const float* scale     = (const float*)d_in[7];
    const float* W1x       = (const float*)d_in[8];
    const float* W1x_d     = (const float*)d_in[9];
    const float* W1x_s     = (const float*)d_in[10];
    const float* W2x       = (const float*)d_in[11];
    const float* W2x_d     = (const float*)d_in[12];
    const float* W3x       = (const float*)d_in[13];
    const float* W1g       = (const float*)d_in[14];
    const float* W1g_d     = (const float*)d_in[15];
    const float* W1g_s     = (const float*)d_in[16];
    const float* W2g       = (const float*)d_in[17];
    const float* W2g_d     = (const float*)d_in[18];
    const float* Wg_vs     = (const float*)d_in[19];
    float* out = (float*)d_out;

    cudaFuncSetAttribute(main_mma, cudaFuncAttributeMaxDynamicSharedMemorySize, SMEM_TOTAL);

    buildW_k<<<5, 256>>>(W1x, W1x_d, W2x, W2x_d, W3x);
    prep_k<<<NB, 128>>>(z_pos, z_dir, z_scalar, gfeat, center, scale,
                        W1x, W1x_s, W1g, W1g_d, W1g_s, W2g, W2g_d, Wg_vs, out);
    argmin_k<<<16, 256>>>(pc);
    main_mma<<<dim3(NM/64, NB), 512, SMEM_TOTAL>>>(point_feat, scale, center, out);
    assemble_k<<<1, 128>>>(out);
}

// round 14
// speedup vs baseline: 1.6922x; 1.2273x over previous
#include <cuda_runtime.h>
#include <cuda_bf16.h>
#include <cstdint>
#include <math.h>

#define EPSN 1e-6f
#define NB 8
#define NM 16384
#define GRIP_OFF (NB*NM*6)
#define AC_OFF   (GRIP_OFF+16)
#define TSP  32
#define ROWB 192                 // bytes per act row (96 bf16)
#define IMG  24576               // act image bytes (128 rows)
#define WOFF_H 49152
#define WOFF_L 81920
#define SMEM_TOTAL 114688        // 112KB -> 2 CTAs/SM

__device__ __align__(16) __nv_bfloat16 g_Whi[5][16384];   // [o][k] row-major
__device__ __align__(16) __nv_bfloat16 g_Wlo[5][16384];
__device__ float g_bias1[NB*128*3];
__device__ float g_s2v1[NB*128];
__device__ float g_grip[NB*2];
__device__ int   g_closest[NB*2];

// ---------------- helpers ----------------
__device__ __forceinline__ uint32_t smem_u32(const void* p){
    uint32_t a; asm("{ .reg .u64 t; cvta.to.shared.u64 t, %1; cvt.u32.u64 %0, t; }" : "=r"(a) : "l"(p)); return a;
}
__device__ __forceinline__ uint32_t pk_bf(float a, float b){
    return (uint32_t)__bfloat16_as_ushort(__float2bfloat16(a)) |
           ((uint32_t)__bfloat16_as_ushort(__float2bfloat16(b)) << 16);
}
__device__ __forceinline__ float bl(uint32_t v){ return __bfloat162float(__ushort_as_bfloat16((unsigned short)(v & 0xFFFF))); }
__device__ __forceinline__ float bhf(uint32_t v){ return __bfloat162float(__ushort_as_bfloat16((unsigned short)(v >> 16))); }

__device__ __forceinline__ void mma_bf16(float* c, const uint32_t* a, uint32_t b0, uint32_t b1){
    asm("mma.sync.aligned.m16n8k16.row.col.f32.bf16.bf16.f32 "
        "{%0,%1,%2,%3},{%4,%5,%6,%7},{%8,%9},{%0,%1,%2,%3};"
        : "+f"(c[0]), "+f"(c[1]), "+f"(c[2]), "+f"(c[3])
        : "r"(a[0]), "r"(a[1]), "r"(a[2]), "r"(a[3]), "r"(b0), "r"(b1));
}
__device__ __forceinline__ void ldsm4t(uint32_t& r0, uint32_t& r1, uint32_t& r2, uint32_t& r3, uint32_t addr){
    asm volatile("ldmatrix.sync.aligned.m8n8.x4.trans.shared.b16 {%0,%1,%2,%3}, [%4];"
        : "=r"(r0), "=r"(r1), "=r"(r2), "=r"(r3) : "r"(addr) : "memory");
}
__device__ __forceinline__ void ldsm4(uint32_t* r, uint32_t addr){
    asm volatile("ldmatrix.sync.aligned.m8n8.x4.shared.b16 {%0,%1,%2,%3}, [%4];"
        : "=r"(r[0]), "=r"(r[1]), "=r"(r[2]), "=r"(r[3]) : "r"(addr) : "memory");
}
__device__ __forceinline__ void cp16(void* dst, const void* src){
    unsigned d = smem_u32(dst);
    asm volatile("cp.async.cg.shared.global [%0], [%1], 16;" :: "r"(d), "l"(src));
}
__device__ __forceinline__ void cpcommit(){ asm volatile("cp.async.commit_group;"); }
__device__ __forceinline__ void cpwait0(){ asm volatile("cp.async.wait_group 0;"); }

// one GEMM layer: 16 o-rows x 6 n8-tiles (16 points), fused 3-term compensation
__device__ __forceinline__ void layer6(float acc[6][4],
    uint32_t WHs, uint32_t WLs, uint32_t sbH, uint32_t sbL,
    int h, int mrow0, int lane)
{
    #pragma unroll
    for (int i = 0; i < 6; i++){ acc[i][0]=0.f; acc[i][1]=0.f; acc[i][2]=0.f; acc[i][3]=0.f; }

    const int rA = lane & 15, keyA = lane & 7, chL = lane >> 4;
    const uint32_t abase = (uint32_t)(mrow0 + rA) * 256;
    const int keyB = (rA >> 1) & 3;
    const uint32_t rowH = sbH + (uint32_t)rA*ROWB;
    const uint32_t rowL = sbL + (uint32_t)rA*ROWB;
    const int clB = h*2 + chL;

    #pragma unroll
    for (int kt = 0; kt < 8; kt++){
        const uint32_t ka = (uint32_t)(((2*kt + chL) ^ keyA) << 4);
        uint32_t aH[4], aL[4];
        ldsm4(aH, WHs + abase + ka);
        ldsm4(aL, WLs + abase + ka);
        const uint32_t kb = (uint32_t)kt*16*ROWB;
        #pragma unroll
        for (int d = 0; d < 3; d++){
            const uint32_t coff = kb + (uint32_t)((d*4 + (clB ^ keyB)) << 4);
            uint32_t b0,b1,b2,b3, l0,l1,l2,l3;
            ldsm4t(b0,b1,b2,b3, rowH + coff);
            ldsm4t(l0,l1,l2,l3, rowL + coff);
            const int j = d*2;
            mma_bf16(acc[j],   aH, b0, b1);
            mma_bf16(acc[j+1], aH, b2, b3);
            mma_bf16(acc[j],   aH, l0, l1);
            mma_bf16(acc[j+1], aH, l2, l3);
            mma_bf16(acc[j],   aL, b0, b1);
            mma_bf16(acc[j+1], aL, b2, b3);
        }
    }
}

// epilogues: MODE 0 = bias+gate, 1 = LNA, 2 = raw copy
template<int MODE>
__device__ __forceinline__ void epi(float acc[6][4], char* sm, int o0, int h, int cb, int bbase)
{
    #pragma unroll
    for (int r = 0; r < 2; r++){
        const int o = o0 + r*8;
        const int keyo = (o >> 1) & 3;
        float b0=0.f, b1=0.f, b2=0.f, sv=0.f;
        if (MODE == 0){
            b0 = g_bias1[(bbase+o)*3+0]; b1 = g_bias1[(bbase+o)*3+1]; b2 = g_bias1[(bbase+o)*3+2];
            sv = g_s2v1[bbase+o];
        }
        #pragma unroll
        for (int u = 0; u < 2; u++){
            uint32_t offd[3];
            #pragma unroll
            for (int d = 0; d < 3; d++)
                offd[d] = (uint32_t)(o*ROWB + ((d*4 + ((h*2+u) ^ keyo)) << 4) + cb*2);
            float x0 = acc[u][2*r],   x1 = acc[u][2*r+1];
            float y0 = acc[2+u][2*r], y1 = acc[2+u][2*r+1];
            float z0 = acc[4+u][2*r], z1 = acc[4+u][2*r+1];
            float h3[3][2];
            if (MODE == 0){
                float q00=x0+b0, q10=y0+b1, q20=z0+b2;
                float q01=x1+b0, q11=y1+b1, q21=z1+b2;
                float g0 = 1.0f + sv/(sqrtf(q00*q00+q10*q10+q20*q20)+EPSN);
                float g1 = 1.0f + sv/(sqrtf(q01*q01+q11*q11+q21*q21)+EPSN);
                h3[0][0]=q00*g0; h3[1][0]=q10*g0; h3[2][0]=q20*g0;
                h3[0][1]=q01*g1; h3[1][1]=q11*g1; h3[2][1]=q21*g1;
            } else if (MODE == 2){
                h3[0][0]=x0; h3[0][1]=x1; h3[1][0]=y0; h3[1][1]=y1; h3[2][0]=z0; h3[2][1]=z1;
            } else {
                float q[3][2];
                #pragma unroll
                for (int d = 0; d < 3; d++){
                    uint32_t qh = *(uint32_t*)(sm + offd[d]);
                    uint32_t ql = *(uint32_t*)(sm + IMG + offd[d]);
                    q[d][0] = bl(qh)+bl(ql); q[d][1] = bhf(qh)+bhf(ql);
                }
                float inv0 = 1.0f/(sqrtf(x0*x0+y0*y0+z0*z0)+EPSN);
                float mf0  = fminf((q[0][0]*x0+q[1][0]*y0+q[2][0]*z0)*inv0, 0.0f)*inv0;
                float inv1 = 1.0f/(sqrtf(x1*x1+y1*y1+z1*z1)+EPSN);
                float mf1  = fminf((q[0][1]*x1+q[1][1]*y1+q[2][1]*z1)*inv1, 0.0f)*inv1;
                h3[0][0]=q[0][0]-mf0*x0; h3[1][0]=q[1][0]-mf0*y0; h3[2][0]=q[2][0]-mf0*z0;
                h3[0][1]=q[0][1]-mf1*x1; h3[1][1]=q[1][1]-mf1*y1; h3[2][1]=q[2][1]-mf1*z1;
            }
            #pragma unroll
            for (int d = 0; d < 3; d++){
                uint32_t hw = pk_bf(h3[d][0], h3[d][1]);
                uint32_t lw = pk_bf(h3[d][0]-bl(hw), h3[d][1]-bhf(hw));
                *(uint32_t*)(sm + offd[d])       = hw;
                *(uint32_t*)(sm + IMG + offd[d]) = lw;
            }
        }
    }
}

// ---------------- main kernel ----------------
__global__ void __launch_bounds__(512, 2)
main_mma(const float* __restrict__ pf, const float* __restrict__ scale,
         const float* __restrict__ center, float* __restrict__ out)
{
    extern __shared__ char sm[];
    const uint32_t sb = smem_u32(sm);
    const uint32_t sbH = sb, sbL = sb + IMG;
    const uint32_t WHs = sb + WOFF_H, WLs = sb + WOFF_L;
    const int tid = threadIdx.x, w = tid >> 5, lane = tid & 31;
    const int b = blockIdx.y, m0 = blockIdx.x * TSP;
    const int og = w >> 1, h = w & 1;
    const int qr = lane >> 2, cb = (lane & 3)*2;

    // stage layer-0 weights (swizzled rows of 256B, key o&7)
    {
        const char* srcH = (const char*)g_Whi[0];
        const char* srcL = (const char*)g_Wlo[0];
        #pragma unroll
        for (int t = 0; t < 4; t++){
            int i = tid + t*512;
            int o = i >> 4, kc = i & 15;
            uint32_t dst = (uint32_t)(o*256 + ((kc ^ (o&7)) << 4));
            cp16(sm + WOFF_H + dst, srcH + (size_t)i*16);
            cp16(sm + WOFF_L + dst, srcL + (size_t)i*16);
        }
        cpcommit();
    }

    // build hi/lo act images: row = channel c, col n = d*32 + p, key (c>>1)&3
    #pragma unroll 1
    for (int it = 0; it < 6; it++){
        int idx = tid + it*512;                 // 0..3071
        int seg = idx & 7, d = (idx >> 3) % 3, c = idx / 24;
        float4 v = __ldg((const float4*)(pf + (((size_t)(b*128+c)*3+d)*NM + m0 + seg*4)));
        uint32_t off = (uint32_t)(c*ROWB + ((d*4 + ((seg>>1) ^ ((c>>1)&3))) << 4) + (seg&1)*8);
        uint2 hv = make_uint2(pk_bf(v.x, v.y), pk_bf(v.z, v.w));
        uint2 lv = make_uint2(pk_bf(v.x - bl(hv.x), v.y - bhf(hv.x)),
                              pk_bf(v.z - bl(hv.y), v.w - bhf(hv.y)));
        *(uint2*)(sm + off)       = hv;
        *(uint2*)(sm + IMG + off) = lv;
    }
    cpwait0();
    __syncthreads();

    float acc[6][4];
    const int o0 = og*16 + qr;
    const int bbase = b*128;

    #pragma unroll 1
    for (int l = 0; l < 4; l++){
        layer6(acc, WHs, WLs, sbH, sbL, h, og*16, lane);
        __syncthreads();
        {   // prefetch next layer's weights during epilogue
            const char* srcH = (const char*)g_Whi[l+1];
            const char* srcL = (const char*)g_Wlo[l+1];
            #pragma unroll
            for (int t = 0; t < 4; t++){
                int i = tid + t*512;
                int o = i >> 4, kc = i & 15;
                uint32_t dst = (uint32_t)(o*256 + ((kc ^ (o&7)) << 4));
                cp16(sm + WOFF_H + dst, srcH + (size_t)i*16);
                cp16(sm + WOFF_L + dst, srcL + (size_t)i*16);
            }
            cpcommit();
        }
        if      (l == 0) epi<0>(acc, sm, o0, h, cb, bbase);
        else if (l == 1) epi<1>(acc, sm, o0, h, cb, bbase);
        else if (l == 2) epi<2>(acc, sm, o0, h, cb, bbase);
        else             epi<1>(acc, sm, o0, h, cb, bbase);
        cpwait0();
        __syncthreads();
    }

    // final projection (W3 padded): og==0 warps; rows 0-1 valid
    if (og == 0){
        layer6(acc, WHs, WLs, sbH, sbL, h, 0, lane);
        if (lane < 8){
            const float sc = __ldg(scale + b);
            const int o2 = qr;   // 0 or 1
            #pragma unroll
            for (int d = 0; d < 3; d++){
                #pragma unroll
                for (int u = 0; u < 2; u++){
                    #pragma unroll
                    for (int j = 0; j < 2; j++){
                        int p = h*16 + u*8 + cb + j;
                        float v = acc[d*2+u][j];
                        if (o2 == 0) v = v*sc + __ldg(center + b*3 + d);
                        out[((size_t)b*NM + m0 + p)*6 + o2*3 + d] = v;
                    }
                }
            }
        }
    }
}

// ---------------- weight split images (40 blocks) ----------------
__global__ void buildW_k(const float* __restrict__ W1x, const float* __restrict__ W1xd,
                         const float* __restrict__ W2x, const float* __restrict__ W2xd,
                         const float* __restrict__ W3x)
{
    const int m = blockIdx.x >> 3, sub = blockIdx.x & 7;
    for (int t = 0; t < 8; t++){
        int i = sub*2048 + threadIdx.x + t*256;
        int o = i >> 7, k = i & 127;
        float w = (m==0) ? W1x[o*136+k] : (m==1) ? W1xd[o*128+k] : (m==2) ? W2x[o*128+k]
                : (m==3) ? W2xd[o*128+k] : ((o<2) ? W3x[o*128+k] : 0.0f);
        __nv_bfloat16 h = __float2bfloat16(w);
        g_Whi[m][i] = h;
        g_Wlo[m][i] = __float2bfloat16(w - __bfloat162float(h));
    }
}

// ---------------- prep: bias/s2v + gripper branch ----------------
__global__ void prep_k(const float* __restrict__ z_pos, const float* __restrict__ z_dir,
                       const float* __restrict__ z_scalar, const float* __restrict__ gfeat,
                       const float* __restrict__ center, const float* __restrict__ scale,
                       const float* __restrict__ W1x, const float* __restrict__ W1x_s,
                       const float* __restrict__ W1g, const float* __restrict__ W1g_d,
                       const float* __restrict__ W1g_s, const float* __restrict__ W2g,
                       const float* __restrict__ W2g_d, const float* __restrict__ Wg_vs,
                       float* __restrict__ out)
{
    __shared__ float vg[136*3], bq[128*3], bhm[128*3], nh[128], zs[8*3];
    const int b = blockIdx.x, o = threadIdx.x;
    if (o < 24){
        int r = o/3, d = o%3;
        zs[r*3+d] = (r < 2) ? (z_pos[(b*2+r)*3+d] - center[b*3+d]) / scale[b] : z_dir[(b*6+(r-2))*3+d];
    }
    __syncthreads();
    {
        g_s2v1[b*128+o] = W1x_s[o*2]*z_scalar[b*2] + W1x_s[o*2+1]*z_scalar[b*2+1];
        #pragma unroll
        for (int d = 0; d < 3; d++){
            float s = 0.0f;
            #pragma unroll
            for (int k = 0; k < 8; k++) s += W1x[o*136 + 128 + k] * zs[k*3+d];
            g_bias1[(b*128+o)*3+d] = s;
        }
    }
    for (int i = o; i < 408; i += 128){
        int c = i/3, d = i%3;
        vg[i] = (c < 128) ? gfeat[(b*128+c)*3+d] : zs[(c-128)*3+d];
    }
    __syncthreads();
    float q[3], dv[3];
    #pragma unroll
    for (int d = 0; d < 3; d++){ float s=0; for (int c=0;c<136;c++) s += W1g[o*136+c]*vg[c*3+d]; q[d]=s; }
    {
        float sg = W1g_s[o*2]*z_scalar[b*2] + W1g_s[o*2+1]*z_scalar[b*2+1];
        float g = 1.0f + sg/(sqrtf(q[0]*q[0]+q[1]*q[1]+q[2]*q[2])+EPSN);
        q[0]*=g; q[1]*=g; q[2]*=g;
    }
    bq[o*3]=q[0]; bq[o*3+1]=q[1]; bq[o*3+2]=q[2];
    __syncthreads();
    #pragma unroll
    for (int d = 0; d < 3; d++){ float s=0; for (int c=0;c<128;c++) s += W1g_d[o*128+c]*bq[c*3+d]; dv[d]=s; }
    {
        float inv = 1.0f/(sqrtf(dv[0]*dv[0]+dv[1]*dv[1]+dv[2]*dv[2]) + EPSN);
        float mf = fminf((q[0]*dv[0]+q[1]*dv[1]+q[2]*dv[2])*inv, 0.0f)*inv;
        q[0]-=mf*dv[0]; q[1]-=mf*dv[1]; q[2]-=mf*dv[2];
    }
    bhm[o*3]=q[0]; bhm[o*3+1]=q[1]; bhm[o*3+2]=q[2];
    __syncthreads();
    #pragma unroll
    for (int d = 0; d < 3; d++){ float s=0; for (int c=0;c<128;c++) s += W2g[o*128+c]*bhm[c*3+d]; q[d]=s; }
    bq[o*3]=q[0]; bq[o*3+1]=q[1]; bq[o*3+2]=q[2];
    __syncthreads();
    #pragma unroll
    for (int d = 0; d < 3; d++){ float s=0; for (int c=0;c<128;c++) s += W2g_d[o*128+c]*bq[c*3+d]; dv[d]=s; }
    {
        float inv = 1.0f/(sqrtf(dv[0]*dv[0]+dv[1]*dv[1]+dv[2]*dv[2]) + EPSN);
        float mf = fminf((q[0]*dv[0]+q[1]*dv[1]+q[2]*dv[2])*inv, 0.0f)*inv;
        q[0]-=mf*dv[0]; q[1]-=mf*dv[1]; q[2]-=mf*dv[2];
    }
    nh[o] = sqrtf(q[0]*q[0]+q[1]*q[1]+q[2]*q[2]);
    __syncthreads();
    if (o < 2){
        float s = 0; for (int c = 0; c < 128; c++) s += Wg_vs[o*128+c]*nh[c];
        float gr = 1.0f/(1.0f+expf(-s));
        g_grip[b*2+o] = gr;
        out[GRIP_OFF + b*2+o] = gr;
    }
}

__global__ void argmin_k(const float* __restrict__ pc, const float* __restrict__ z_pos,
                         const float* __restrict__ center, const float* __restrict__ scale)
{
    __shared__ float sv[256]; __shared__ int si[256];
    const int be = blockIdx.x, b = be >> 1;
    const float inv = 1.0f / scale[b];
    const float zx = (z_pos[be*3+0] - center[b*3+0]) * inv;
    const float zy = (z_pos[be*3+1] - center[b*3+1]) * inv;
    const float zz = (z_pos[be*3+2] - center[b*3+2]) * inv;
    const float* p = pc + (size_t)b*NM*3;
    float best = 3.4e38f; int bi = 0;
    for (int m = threadIdx.x; m < NM; m += blockDim.x){
        float dx=zx-p[m*3], dy=zy-p[m*3+1], dz=zz-p[m*3+2];
        float d = sqrtf(dx*dx+dy*dy+dz*dz);
        if (d < best){ best = d; bi = m; }
    }
    sv[threadIdx.x]=best; si[threadIdx.x]=bi;
    __syncthreads();
    for (int s = 128; s > 0; s >>= 1){
        if (threadIdx.x < s){
            float ov = sv[threadIdx.x+s]; int oi = si[threadIdx.x+s];
            if (ov < sv[threadIdx.x] || (ov == sv[threadIdx.x] && oi < si[threadIdx.x])){
                sv[threadIdx.x]=ov; si[threadIdx.x]=oi;
            }
        }
        __syncthreads();
    }
    if (threadIdx.x == 0) g_closest[be] = si[0];
}

__global__ void assemble_k(float* __restrict__ out)
{
    const int t = threadIdx.x;
    if (t < 112){
        int b = t/14, j = t%14, e = j/7, r = j%7;
        float v;
        if (r == 0) v = g_grip[b*2+e];
        else { int m = g_closest[b*2+e]; v = out[((size_t)b*NM+m)*6 + (r-1)]; }
        out[AC_OFF + t] = v;
    }
}

// ---------------- launch ----------------
extern "C" void kernel_launch(void* const* d_in, const int* in_sizes, int n_in,
                              void* d_out, int out_size)
{
    const float* pc        = (const float*)d_in[0];
    const float* z_pos     = (const float*)d_in[1];
    const float* z_dir     = (const float*)d_in[2];
    const float* z_scalar  = (const float*)d_in[3];
    const float* point_feat= (const float*)d_in[4];
    const float* gfeat     = (const float*)d_in[5];
    const float* center    = (const float*)d_in[6];
    const float* scale     = (const float*)d_in[7];
    const float* W1x       = (const float*)d_in[8];
    const float* W1x_d     = (const float*)d_in[9];
    const float* W1x_s     = (const float*)d_in[10];
    const float* W2x       = (const float*)d_in[11];
    const float* W2x_d     = (const float*)d_in[12];
    const float* W3x       = (const float*)d_in[13];
    const float* W1g       = (const float*)d_in[14];
    const float* W1g_d     = (const float*)d_in[15];
    const float* W1g_s     = (const float*)d_in[16];
    const float* W2g       = (const float*)d_in[17];
    const float* W2g_d     = (const float*)d_in[18];
    const float* Wg_vs     = (const float*)d_in[19];
    float* out = (float*)d_out;

    cudaFuncSetAttribute(main_mma, cudaFuncAttributeMaxDynamicSharedMemorySize, SMEM_TOTAL);

    buildW_k<<<40, 256>>>(W1x, W1x_d, W2x, W2x_d, W3x);
    prep_k<<<NB, 128>>>(z_pos, z_dir, z_scalar, gfeat, center, scale,
                        W1x, W1x_s, W1g, W1g_d, W1g_s, W2g, W2g_d, Wg_vs, out);
    argmin_k<<<16, 256>>>(pc, z_pos, center, scale);
    main_mma<<<dim3(NM/TSP, NB), 512, SMEM_TOTAL>>>(point_feat, scale, center, out);
    assemble_k<<<1, 128>>>(out);
}

// round 15
// speedup vs baseline: 2.0760x; 1.2268x over previous
#include <cuda_runtime.h>
#include <cuda_bf16.h>
#include <cuda_fp16.h>
#include <cstdint>
#include <math.h>

#define EPSN 1e-6f
#define NB 8
#define NM 16384
#define GRIP_OFF (NB*NM*6)
#define AC_OFF   (GRIP_OFF+16)
#define TSP  32
#define ROWB 192                 // bytes per act row (96 fp16)
#define IMG  24576               // act image bytes (128 rows)
#define WOFF 49152               // weight stage (32KB, single fp16)
#define SMEM_TOTAL 81920

__device__ __align__(16) __half g_W16[5][16384];   // [o][k] row-major fp16
__device__ float g_bias1[NB*128*3];
__device__ float g_s2v1[NB*128];
__device__ float g_grip[NB*2];
__device__ int   g_closest[NB*2];

// ---------------- helpers ----------------
__device__ __forceinline__ uint32_t smem_u32(const void* p){
    uint32_t a; asm("{ .reg .u64 t; cvta.to.shared.u64 t, %1; cvt.u32.u64 %0, t; }" : "=r"(a) : "l"(p)); return a;
}
__device__ __forceinline__ uint32_t pk_hf(float a, float b){
    return (uint32_t)__half_as_ushort(__float2half_rn(a)) |
           ((uint32_t)__half_as_ushort(__float2half_rn(b)) << 16);
}
__device__ __forceinline__ float hl(uint32_t v){ return __half2float(__ushort_as_half((unsigned short)(v & 0xFFFF))); }
__device__ __forceinline__ float hh(uint32_t v){ return __half2float(__ushort_as_half((unsigned short)(v >> 16))); }

__device__ __forceinline__ void mma_f16(float* c, const uint32_t* a, uint32_t b0, uint32_t b1){
    asm("mma.sync.aligned.m16n8k16.row.col.f32.f16.f16.f32 "
        "{%0,%1,%2,%3},{%4,%5,%6,%7},{%8,%9},{%0,%1,%2,%3};"
        : "+f"(c[0]), "+f"(c[1]), "+f"(c[2]), "+f"(c[3])
        : "r"(a[0]), "r"(a[1]), "r"(a[2]), "r"(a[3]), "r"(b0), "r"(b1));
}
__device__ __forceinline__ void ldsm4t(uint32_t& r0, uint32_t& r1, uint32_t& r2, uint32_t& r3, uint32_t addr){
    asm volatile("ldmatrix.sync.aligned.m8n8.x4.trans.shared.b16 {%0,%1,%2,%3}, [%4];"
        : "=r"(r0), "=r"(r1), "=r"(r2), "=r"(r3) : "r"(addr) : "memory");
}
__device__ __forceinline__ void ldsm4(uint32_t* r, uint32_t addr){
    asm volatile("ldmatrix.sync.aligned.m8n8.x4.shared.b16 {%0,%1,%2,%3}, [%4];"
        : "=r"(r[0]), "=r"(r[1]), "=r"(r[2]), "=r"(r[3]) : "r"(addr) : "memory");
}
__device__ __forceinline__ void cp16(void* dst, const void* src){
    unsigned d = smem_u32(dst);
    asm volatile("cp.async.cg.shared.global [%0], [%1], 16;" :: "r"(d), "l"(src));
}
__device__ __forceinline__ void cpcommit(){ asm volatile("cp.async.commit_group;"); }
__device__ __forceinline__ void cpwait0(){ asm volatile("cp.async.wait_group 0;"); }

// one GEMM layer: NAT A-tiles (16 rows) x (8 points x 3 d), 2-pass xhi/xlo, W single fp16
template<int NAT>
__device__ __forceinline__ void layer2p(float acc[NAT][3][4],
    uint32_t Ws, uint32_t sbA, int pq, int mrow0, int lane)
{
    #pragma unroll
    for (int at = 0; at < NAT; at++)
        #pragma unroll
        for (int d = 0; d < 3; d++){ acc[at][d][0]=0.f; acc[at][d][1]=0.f; acc[at][d][2]=0.f; acc[at][d][3]=0.f; }

    const int rr = lane & 15, chA = lane >> 4, keyA = lane & 7;
    const int keyB = (rr >> 1) & 3;
    // B paired addressing: lanes 0-15 -> hi image, lanes 16-31 -> lo image, same rows
    const uint32_t brow = sbA + ((lane >= 16) ? (uint32_t)IMG : 0u) + (uint32_t)rr*ROWB;

    #pragma unroll
    for (int kt = 0; kt < 8; kt++){
        const uint32_t ka = (uint32_t)(((2*kt + chA) ^ keyA) << 4);
        uint32_t a0[4], a1[4];
        ldsm4(a0, Ws + (uint32_t)(mrow0 + rr)*256 + ka);
        if (NAT == 2) ldsm4(a1, Ws + (uint32_t)(mrow0 + 16 + rr)*256 + ka);
        const uint32_t kb = (uint32_t)kt*16*ROWB;
        #pragma unroll
        for (int d = 0; d < 3; d++){
            const uint32_t coff = kb + (uint32_t)((d*4 + (pq ^ keyB)) << 4);
            uint32_t b0,b1,b2,b3;                 // {b0,b1}=xhi, {b2,b3}=xlo
            ldsm4t(b0,b1,b2,b3, brow + coff);
            mma_f16(acc[0][d], a0, b0, b1);
            mma_f16(acc[0][d], a0, b2, b3);
            if (NAT == 2){
                mma_f16(acc[1][d], a1, b0, b1);
                mma_f16(acc[1][d], a1, b2, b3);
            }
        }
    }
}

// epilogues: MODE 0 = bias+gate, 1 = LNA, 2 = raw copy
template<int MODE>
__device__ __forceinline__ void epi(float acc[2][3][4], char* sm, int mrow0, int pq,
                                    int qr, int cb, int bbase)
{
    #pragma unroll
    for (int at = 0; at < 2; at++){
        #pragma unroll
        for (int r = 0; r < 2; r++){
            const int o = mrow0 + at*16 + qr + r*8;
            const int keyo = (o >> 1) & 3;
            float b0=0.f, b1=0.f, b2=0.f, sv=0.f;
            if (MODE == 0){
                b0 = g_bias1[(bbase+o)*3+0]; b1 = g_bias1[(bbase+o)*3+1]; b2 = g_bias1[(bbase+o)*3+2];
                sv = g_s2v1[bbase+o];
            }
            uint32_t offd[3];
            #pragma unroll
            for (int d = 0; d < 3; d++)
                offd[d] = (uint32_t)(o*ROWB + ((d*4 + (pq ^ keyo)) << 4) + cb*2);
            float x0 = acc[at][0][2*r], x1 = acc[at][0][2*r+1];
            float y0 = acc[at][1][2*r], y1 = acc[at][1][2*r+1];
            float z0 = acc[at][2][2*r], z1 = acc[at][2][2*r+1];
            float h3[3][2];
            if (MODE == 0){
                float q00=x0+b0, q10=y0+b1, q20=z0+b2;
                float q01=x1+b0, q11=y1+b1, q21=z1+b2;
                float g0 = 1.0f + sv/(sqrtf(q00*q00+q10*q10+q20*q20)+EPSN);
                float g1 = 1.0f + sv/(sqrtf(q01*q01+q11*q11+q21*q21)+EPSN);
                h3[0][0]=q00*g0; h3[1][0]=q10*g0; h3[2][0]=q20*g0;
                h3[0][1]=q01*g1; h3[1][1]=q11*g1; h3[2][1]=q21*g1;
            } else if (MODE == 2){
                h3[0][0]=x0; h3[0][1]=x1; h3[1][0]=y0; h3[1][1]=y1; h3[2][0]=z0; h3[2][1]=z1;
            } else {
                float q[3][2];
                #pragma unroll
                for (int d = 0; d < 3; d++){
                    uint32_t qh = *(uint32_t*)(sm + offd[d]);
                    uint32_t ql = *(uint32_t*)(sm + IMG + offd[d]);
                    q[d][0] = hl(qh)+hl(ql); q[d][1] = hh(qh)+hh(ql);
                }
                float inv0 = 1.0f/(sqrtf(x0*x0+y0*y0+z0*z0)+EPSN);
                float mf0  = fminf((q[0][0]*x0+q[1][0]*y0+q[2][0]*z0)*inv0, 0.0f)*inv0;
                float inv1 = 1.0f/(sqrtf(x1*x1+y1*y1+z1*z1)+EPSN);
                float mf1  = fminf((q[0][1]*x1+q[1][1]*y1+q[2][1]*z1)*inv1, 0.0f)*inv1;
                h3[0][0]=q[0][0]-mf0*x0; h3[1][0]=q[1][0]-mf0*y0; h3[2][0]=q[2][0]-mf0*z0;
                h3[0][1]=q[0][1]-mf1*x1; h3[1][1]=q[1][1]-mf1*y1; h3[2][1]=q[2][1]-mf1*z1;
            }
            #pragma unroll
            for (int d = 0; d < 3; d++){
                uint32_t hw = pk_hf(h3[d][0], h3[d][1]);
                uint32_t lw = pk_hf(h3[d][0]-hl(hw), h3[d][1]-hh(hw));
                *(uint32_t*)(sm + offd[d])       = hw;
                *(uint32_t*)(sm + IMG + offd[d]) = lw;
            }
        }
    }
}

// ---------------- main kernel ----------------
__global__ void __launch_bounds__(512, 2)
main_mma(const float* __restrict__ pf, const float* __restrict__ scale,
         const float* __restrict__ center, float* __restrict__ out)
{
    extern __shared__ char sm[];
    const uint32_t sb = smem_u32(sm);
    const uint32_t Ws = sb + WOFF;
    const int tid = threadIdx.x, w = tid >> 5, lane = tid & 31;
    const int b = blockIdx.y, m0 = blockIdx.x * TSP;
    const int mg = w >> 2, pq = w & 3;
    const int qr = lane >> 2, cb = (lane & 3)*2;

    // stage layer-0 weights (swizzled 256B rows, key o&7)
    {
        const char* src = (const char*)g_W16[0];
        #pragma unroll
        for (int t = 0; t < 4; t++){
            int i = tid + t*512;
            int o = i >> 4, kc = i & 15;
            cp16(sm + WOFF + (uint32_t)(o*256 + ((kc ^ (o&7)) << 4)), src + (size_t)i*16);
        }
        cpcommit();
    }

    // build hi/lo act images: row = channel c, col n = d*32+p, key (c>>1)&3
    #pragma unroll 1
    for (int it = 0; it < 6; it++){
        int idx = tid + it*512;
        int seg = idx & 7, d = (idx >> 3) % 3, c = idx / 24;
        float4 v = __ldg((const float4*)(pf + (((size_t)(b*128+c)*3+d)*NM + m0 + seg*4)));
        uint32_t off = (uint32_t)(c*ROWB + ((d*4 + ((seg>>1) ^ ((c>>1)&3))) << 4) + (seg&1)*8);
        uint2 hv = make_uint2(pk_hf(v.x, v.y), pk_hf(v.z, v.w));
        uint2 lv = make_uint2(pk_hf(v.x - hl(hv.x), v.y - hh(hv.x)),
                              pk_hf(v.z - hl(hv.y), v.w - hh(hv.y)));
        *(uint2*)(sm + off)       = hv;
        *(uint2*)(sm + IMG + off) = lv;
    }
    cpwait0();
    __syncthreads();

    float acc[2][3][4];
    const int bbase = b*128;

    #pragma unroll 1
    for (int l = 0; l < 4; l++){
        layer2p<2>(acc, Ws, sb, pq, mg*32, lane);
        __syncthreads();
        {   // prefetch next layer's weights during epilogue
            const char* src = (const char*)g_W16[l+1];
            #pragma unroll
            for (int t = 0; t < 4; t++){
                int i = tid + t*512;
                int o = i >> 4, kc = i & 15;
                cp16(sm + WOFF + (uint32_t)(o*256 + ((kc ^ (o&7)) << 4)), src + (size_t)i*16);
            }
            cpcommit();
        }
        if      (l == 0) epi<0>(acc, sm, mg*32, pq, qr, cb, bbase);
        else if (l == 1) epi<1>(acc, sm, mg*32, pq, qr, cb, bbase);
        else if (l == 2) epi<2>(acc, sm, mg*32, pq, qr, cb, bbase);
        else             epi<1>(acc, sm, mg*32, pq, qr, cb, bbase);
        cpwait0();
        __syncthreads();
    }

    // final projection (W3 padded to 128 rows; rows 0-1 valid): mg==0 warps only
    if (mg == 0){
        float facc[1][3][4];
        layer2p<1>(facc, Ws, sb, pq, 0, lane);
        if (lane < 8){
            const float sc = __ldg(scale + b);
            const int o2 = qr;   // 0 or 1
            #pragma unroll
            for (int d = 0; d < 3; d++){
                #pragma unroll
                for (int j = 0; j < 2; j++){
                    int p = pq*8 + cb + j;
                    float v = facc[0][d][j];
                    if (o2 == 0) v = v*sc + __ldg(center + b*3 + d);
                    out[((size_t)b*NM + m0 + p)*6 + o2*3 + d] = v;
                }
            }
        }
    }
}

// ---------------- weight fp16 images (40 blocks) ----------------
__global__ void buildW_k(const float* __restrict__ W1x, const float* __restrict__ W1xd,
                         const float* __restrict__ W2x, const float* __restrict__ W2xd,
                         const float* __restrict__ W3x)
{
    const int m = blockIdx.x >> 3, sub = blockIdx.x & 7;
    for (int t = 0; t < 8; t++){
        int i = sub*2048 + threadIdx.x + t*256;
        int o = i >> 7, k = i & 127;
        float w = (m==0) ? W1x[o*136+k] : (m==1) ? W1xd[o*128+k] : (m==2) ? W2x[o*128+k]
                : (m==3) ? W2xd[o*128+k] : ((o<2) ? W3x[o*128+k] : 0.0f);
        g_W16[m][i] = __float2half_rn(w);
    }
}

// ---------------- prep: bias/s2v + gripper branch ----------------
__global__ void prep_k(const float* __restrict__ z_pos, const float* __restrict__ z_dir,
                       const float* __restrict__ z_scalar, const float* __restrict__ gfeat,
                       const float* __restrict__ center, const float* __restrict__ scale,
                       const float* __restrict__ W1x, const float* __restrict__ W1x_s,
                       const float* __restrict__ W1g, const float* __restrict__ W1g_d,
                       const float* __restrict__ W1g_s, const float* __restrict__ W2g,
                       const float* __restrict__ W2g_d, const float* __restrict__ Wg_vs,
                       float* __restrict__ out)
{
    __shared__ float vg[136*3], bq[128*3], bhm[128*3], nh[128], zs[8*3];
    const int b = blockIdx.x, o = threadIdx.x;
    if (o < 24){
        int r = o/3, d = o%3;
        zs[r*3+d] = (r < 2) ? (z_pos[(b*2+r)*3+d] - center[b*3+d]) / scale[b] : z_dir[(b*6+(r-2))*3+d];
    }
    __syncthreads();
    {
        g_s2v1[b*128+o] = W1x_s[o*2]*z_scalar[b*2] + W1x_s[o*2+1]*z_scalar[b*2+1];
        #pragma unroll
        for (int d = 0; d < 3; d++){
            float s = 0.0f;
            #pragma unroll
            for (int k = 0; k < 8; k++) s += W1x[o*136 + 128 + k] * zs[k*3+d];
            g_bias1[(b*128+o)*3+d] = s;
        }
    }
    for (int i = o; i < 408; i += 128){
        int c = i/3, d = i%3;
        vg[i] = (c < 128) ? gfeat[(b*128+c)*3+d] : zs[(c-128)*3+d];
    }
    __syncthreads();
    float q[3], dv[3];
    #pragma unroll
    for (int d = 0; d < 3; d++){ float s=0; for (int c=0;c<136;c++) s += W1g[o*136+c]*vg[c*3+d]; q[d]=s; }
    {
        float sg = W1g_s[o*2]*z_scalar[b*2] + W1g_s[o*2+1]*z_scalar[b*2+1];
        float g = 1.0f + sg/(sqrtf(q[0]*q[0]+q[1]*q[1]+q[2]*q[2])+EPSN);
        q[0]*=g; q[1]*=g; q[2]*=g;
    }
    bq[o*3]=q[0]; bq[o*3+1]=q[1]; bq[o*3+2]=q[2];
    __syncthreads();
    #pragma unroll
    for (int d = 0; d < 3; d++){ float s=0; for (int c=0;c<128;c++) s += W1g_d[o*128+c]*bq[c*3+d]; dv[d]=s; }
    {
        float inv = 1.0f/(sqrtf(dv[0]*dv[0]+dv[1]*dv[1]+dv[2]*dv[2]) + EPSN);
        float mf = fminf((q[0]*dv[0]+q[1]*dv[1]+q[2]*dv[2])*inv, 0.0f)*inv;
        q[0]-=mf*dv[0]; q[1]-=mf*dv[1]; q[2]-=mf*dv[2];
    }
    bhm[o*3]=q[0]; bhm[o*3+1]=q[1]; bhm[o*3+2]=q[2];
    __syncthreads();
    #pragma unroll
    for (int d = 0; d < 3; d++){ float s=0; for (int c=0;c<128;c++) s += W2g[o*128+c]*bhm[c*3+d]; q[d]=s; }
    bq[o*3]=q[0]; bq[o*3+1]=q[1]; bq[o*3+2]=q[2];
    __syncthreads();
    #pragma unroll
    for (int d = 0; d < 3; d++){ float s=0; for (int c=0;c<128;c++) s += W2g_d[o*128+c]*bq[c*3+d]; dv[d]=s; }
    {
        float inv = 1.0f/(sqrtf(dv[0]*dv[0]+dv[1]*dv[1]+dv[2]*dv[2]) + EPSN);
        float mf = fminf((q[0]*dv[0]+q[1]*dv[1]+q[2]*dv[2])*inv, 0.0f)*inv;
        q[0]-=mf*dv[0]; q[1]-=mf*dv[1]; q[2]-=mf*dv[2];
    }
    nh[o] = sqrtf(q[0]*q[0]+q[1]*q[1]+q[2]*q[2]);
    __syncthreads();
    if (o < 2){
        float s = 0; for (int c = 0; c < 128; c++) s += Wg_vs[o*128+c]*nh[c];
        float gr = 1.0f/(1.0f+expf(-s));
        g_grip[b*2+o] = gr;
        out[GRIP_OFF + b*2+o] = gr;
    }
}

__global__ void argmin_k(const float* __restrict__ pc, const float* __restrict__ z_pos,
                         const float* __restrict__ center, const float* __restrict__ scale)
{
    __shared__ float sv[256]; __shared__ int si[256];
    const int be = blockIdx.x, b = be >> 1;
    const float inv = 1.0f / scale[b];
    const float zx = (z_pos[be*3+0] - center[b*3+0]) * inv;
    const float zy = (z_pos[be*3+1] - center[b*3+1]) * inv;
    const float zz = (z_pos[be*3+2] - center[b*3+2]) * inv;
    const float* p = pc + (size_t)b*NM*3;
    float best = 3.4e38f; int bi = 0;
    for (int m = threadIdx.x; m < NM; m += blockDim.x){
        float dx=zx-p[m*3], dy=zy-p[m*3+1], dz=zz-p[m*3+2];
        float d = sqrtf(dx*dx+dy*dy+dz*dz);
        if (d < best){ best = d; bi = m; }
    }
    sv[threadIdx.x]=best; si[threadIdx.x]=bi;
    __syncthreads();
    for (int s = 128; s > 0; s >>= 1){
        if (threadIdx.x < s){
            float ov = sv[threadIdx.x+s]; int oi = si[threadIdx.x+s];
            if (ov < sv[threadIdx.x] || (ov == sv[threadIdx.x] && oi < si[threadIdx.x])){
                sv[threadIdx.x]=ov; si[threadIdx.x]=oi;
            }
        }
        __syncthreads();
    }
    if (threadIdx.x == 0) g_closest[be] = si[0];
}

__global__ void assemble_k(float* __restrict__ out)
{
    const int t = threadIdx.x;
    if (t < 112){
        int b = t/14, j = t%14, e = j/7, r = j%7;
        float v;
        if (r == 0) v = g_grip[b*2+e];
        else { int m = g_closest[b*2+e]; v = out[((size_t)b*NM+m)*6 + (r-1)]; }
        out[AC_OFF + t] = v;
    }
}

// ---------------- launch ----------------
extern "C" void kernel_launch(void* const* d_in, const int* in_sizes, int n_in,
                              void* d_out, int out_size)
{
    const float* pc        = (const float*)d_in[0];
    const float* z_pos     = (const float*)d_in[1];
    const float* z_dir     = (const float*)d_in[2];
    const float* z_scalar  = (const float*)d_in[3];
    const float* point_feat= (const float*)d_in[4];
    const float* gfeat     = (const float*)d_in[5];
    const float* center    = (const float*)d_in[6];
    const float* scale     = (const float*)d_in[7];
    const float* W1x       = (const float*)d_in[8];
    const float* W1x_d     = (const float*)d_in[9];
    const float* W1x_s     = (const float*)d_in[10];
    const float* W2x       = (const float*)d_in[11];
    const float* W2x_d     = (const float*)d_in[12];
    const float* W3x       = (const float*)d_in[13];
    const float* W1g       = (const float*)d_in[14];
    const float* W1g_d     = (const float*)d_in[15];
    const float* W1g_s     = (const float*)d_in[16];
    const float* W2g       = (const float*)d_in[17];
    const float* W2g_d     = (const float*)d_in[18];
    const float* Wg_vs     = (const float*)d_in[19];
    float* out = (float*)d_out;

    cudaFuncSetAttribute(main_mma, cudaFuncAttributeMaxDynamicSharedMemorySize, SMEM_TOTAL);

    buildW_k<<<40, 256>>>(W1x, W1x_d, W2x, W2x_d, W3x);
    prep_k<<<NB, 128>>>(z_pos, z_dir, z_scalar, gfeat, center, scale,
                        W1x, W1x_s, W1g, W1g_d, W1g_s, W2g, W2g_d, Wg_vs, out);
    argmin_k<<<16, 256>>>(pc, z_pos, center, scale);
    main_mma<<<dim3(NM/TSP, NB), 512, SMEM_TOTAL>>>(point_feat, scale, center, out);
    assemble_k<<<1, 128>>>(out);
}

// round 16
// speedup vs baseline: 2.2656x; 1.0913x over previous
#include <cuda_runtime.h>
#include <cuda_bf16.h>
#include <cuda_fp16.h>
#include <cstdint>
#include <math.h>

#define EPSN 1e-6f
#define NB 8
#define NM 16384
#define GRIP_OFF (NB*NM*6)
#define AC_OFF   (GRIP_OFF+16)
#define TSP  32
#define ROWB 192                 // bytes per act row (96 fp16)
#define IMG  24576               // act image bytes (128 rows)
#define WOFF 49152               // weight stage (32KB fp16)
#define SMEM_TOTAL 81920

__device__ __align__(16) __half g_W16[5][16384];   // [o][k] row-major fp16
__device__ float g_bias1[NB*128*3];
__device__ float g_s2v1[NB*128];
__device__ float g_grip[NB*2];
__device__ int   g_closest[NB*2];

// ---------------- helpers ----------------
__device__ __forceinline__ uint32_t smem_u32(const void* p){
    uint32_t a; asm("{ .reg .u64 t; cvta.to.shared.u64 t, %1; cvt.u32.u64 %0, t; }" : "=r"(a) : "l"(p)); return a;
}
__device__ __forceinline__ uint32_t pk_hf(float a, float b){
    return (uint32_t)__half_as_ushort(__float2half_rn(a)) |
           ((uint32_t)__half_as_ushort(__float2half_rn(b)) << 16);
}
__device__ __forceinline__ float hl(uint32_t v){ return __half2float(__ushort_as_half((unsigned short)(v & 0xFFFF))); }
__device__ __forceinline__ float hh(uint32_t v){ return __half2float(__ushort_as_half((unsigned short)(v >> 16))); }

__device__ __forceinline__ void mma_f16(float* c, const uint32_t* a, uint32_t b0, uint32_t b1){
    asm("mma.sync.aligned.m16n8k16.row.col.f32.f16.f16.f32 "
        "{%0,%1,%2,%3},{%4,%5,%6,%7},{%8,%9},{%0,%1,%2,%3};"
        : "+f"(c[0]), "+f"(c[1]), "+f"(c[2]), "+f"(c[3])
        : "r"(a[0]), "r"(a[1]), "r"(a[2]), "r"(a[3]), "r"(b0), "r"(b1));
}
__device__ __forceinline__ void ldsm4t(uint32_t& r0, uint32_t& r1, uint32_t& r2, uint32_t& r3, uint32_t addr){
    asm volatile("ldmatrix.sync.aligned.m8n8.x4.trans.shared.b16 {%0,%1,%2,%3}, [%4];"
        : "=r"(r0), "=r"(r1), "=r"(r2), "=r"(r3) : "r"(addr) : "memory");
}
__device__ __forceinline__ void ldsm4(uint32_t* r, uint32_t addr){
    asm volatile("ldmatrix.sync.aligned.m8n8.x4.shared.b16 {%0,%1,%2,%3}, [%4];"
        : "=r"(r[0]), "=r"(r[1]), "=r"(r[2]), "=r"(r[3]) : "r"(addr) : "memory");
}
__device__ __forceinline__ void cp16(void* dst, const void* src){
    unsigned d = smem_u32(dst);
    asm volatile("cp.async.cg.shared.global [%0], [%1], 16;" :: "r"(d), "l"(src));
}
__device__ __forceinline__ void cpcommit(){ asm volatile("cp.async.commit_group;"); }
__device__ __forceinline__ void cpwait0(){ asm volatile("cp.async.wait_group 0;"); }

// one GEMM layer: NAT A-tiles (16 rows) x (8 points x 3 d), 2-pass xhi/xlo
template<int NAT>
__device__ __forceinline__ void layer2p(float acc[NAT][3][4],
    uint32_t Ws, uint32_t sbA, int pq, int mrow0, int lane)
{
    #pragma unroll
    for (int at = 0; at < NAT; at++)
        #pragma unroll
        for (int d = 0; d < 3; d++){ acc[at][d][0]=0.f; acc[at][d][1]=0.f; acc[at][d][2]=0.f; acc[at][d][3]=0.f; }

    const int rr = lane & 15, chA = lane >> 4, keyA = lane & 7;
    const int keyB = (rr >> 1) & 3;
    const uint32_t brow = sbA + ((lane >= 16) ? (uint32_t)IMG : 0u) + (uint32_t)rr*ROWB;
    const uint32_t ab0 = Ws + (uint32_t)(mrow0 + rr)*256;
    const uint32_t ab1 = ab0 + 16*256;
    uint32_t coffs[3];
    #pragma unroll
    for (int d = 0; d < 3; d++) coffs[d] = (uint32_t)((d*4 + (pq ^ keyB)) << 4);

    #pragma unroll
    for (int kt = 0; kt < 8; kt++){
        const uint32_t ka = (uint32_t)(((2*kt + chA) ^ keyA) << 4);
        uint32_t a0[4], a1[4];
        ldsm4(a0, ab0 + ka);
        if (NAT == 2) ldsm4(a1, ab1 + ka);
        const uint32_t kb = brow + (uint32_t)kt*16*ROWB;
        #pragma unroll
        for (int d = 0; d < 3; d++){
            uint32_t b0,b1,b2,b3;                 // {b0,b1}=xhi, {b2,b3}=xlo
            ldsm4t(b0,b1,b2,b3, kb + coffs[d]);
            mma_f16(acc[0][d], a0, b0, b1);
            mma_f16(acc[0][d], a0, b2, b3);
            if (NAT == 2){
                mma_f16(acc[1][d], a1, b0, b1);
                mma_f16(acc[1][d], a1, b2, b3);
            }
        }
    }
}

// epilogues: MODE 0 = bias+gate, 1 = LNA, 2 = raw copy
template<int MODE>
__device__ __forceinline__ void epi(float acc[2][3][4], char* sm, int mrow0, int pq,
                                    int qr, int cb, int bbase)
{
    #pragma unroll
    for (int at = 0; at < 2; at++){
        #pragma unroll
        for (int r = 0; r < 2; r++){
            const int o = mrow0 + at*16 + qr + r*8;
            const int keyo = (o >> 1) & 3;
            float b0=0.f, b1=0.f, b2=0.f, sv=0.f;
            if (MODE == 0){
                b0 = g_bias1[(bbase+o)*3+0]; b1 = g_bias1[(bbase+o)*3+1]; b2 = g_bias1[(bbase+o)*3+2];
                sv = g_s2v1[bbase+o];
            }
            uint32_t offd[3];
            #pragma unroll
            for (int d = 0; d < 3; d++)
                offd[d] = (uint32_t)(o*ROWB + ((d*4 + (pq ^ keyo)) << 4) + cb*2);
            float x0 = acc[at][0][2*r], x1 = acc[at][0][2*r+1];
            float y0 = acc[at][1][2*r], y1 = acc[at][1][2*r+1];
            float z0 = acc[at][2][2*r], z1 = acc[at][2][2*r+1];
            float h3[3][2];
            if (MODE == 0){
                float q00=x0+b0, q10=y0+b1, q20=z0+b2;
                float q01=x1+b0, q11=y1+b1, q21=z1+b2;
                float g0 = 1.0f + sv/(sqrtf(q00*q00+q10*q10+q20*q20)+EPSN);
                float g1 = 1.0f + sv/(sqrtf(q01*q01+q11*q11+q21*q21)+EPSN);
                h3[0][0]=q00*g0; h3[1][0]=q10*g0; h3[2][0]=q20*g0;
                h3[0][1]=q01*g1; h3[1][1]=q11*g1; h3[2][1]=q21*g1;
            } else if (MODE == 2){
                h3[0][0]=x0; h3[0][1]=x1; h3[1][0]=y0; h3[1][1]=y1; h3[2][0]=z0; h3[2][1]=z1;
            } else {
                float q[3][2];
                #pragma unroll
                for (int d = 0; d < 3; d++){
                    uint32_t qh = *(uint32_t*)(sm + offd[d]);
                    uint32_t ql = *(uint32_t*)(sm + IMG + offd[d]);
                    q[d][0] = hl(qh)+hl(ql); q[d][1] = hh(qh)+hh(ql);
                }
                float inv0 = 1.0f/(sqrtf(x0*x0+y0*y0+z0*z0)+EPSN);
                float mf0  = fminf((q[0][0]*x0+q[1][0]*y0+q[2][0]*z0)*inv0, 0.0f)*inv0;
                float inv1 = 1.0f/(sqrtf(x1*x1+y1*y1+z1*z1)+EPSN);
                float mf1  = fminf((q[0][1]*x1+q[1][1]*y1+q[2][1]*z1)*inv1, 0.0f)*inv1;
                h3[0][0]=q[0][0]-mf0*x0; h3[1][0]=q[1][0]-mf0*y0; h3[2][0]=q[2][0]-mf0*z0;
                h3[0][1]=q[0][1]-mf1*x1; h3[1][1]=q[1][1]-mf1*y1; h3[2][1]=q[2][1]-mf1*z1;
            }
            #pragma unroll
            for (int d = 0; d < 3; d++){
                uint32_t hw = pk_hf(h3[d][0], h3[d][1]);
                uint32_t lw = pk_hf(h3[d][0]-hl(hw), h3[d][1]-hh(hw));
                *(uint32_t*)(sm + offd[d])       = hw;
                *(uint32_t*)(sm + IMG + offd[d]) = lw;
            }
        }
    }
}

// ---------------- main kernel ----------------
__global__ void __launch_bounds__(512, 2)
main_mma(const float* __restrict__ pf, const float* __restrict__ scale,
         const float* __restrict__ center, float* __restrict__ out)
{
    extern __shared__ char sm[];
    const uint32_t sb = smem_u32(sm);
    const uint32_t Ws = sb + WOFF;
    const int tid = threadIdx.x, w = tid >> 5, lane = tid & 31;
    const int b = blockIdx.y, m0 = blockIdx.x * TSP;
    const int mg = w >> 2, pq = w & 3;
    const int qr = lane >> 2, cb = (lane & 3)*2;

    {
        const char* src = (const char*)g_W16[0];
        #pragma unroll
        for (int t = 0; t < 4; t++){
            int i = tid + t*512;
            int o = i >> 4, kc = i & 15;
            cp16(sm + WOFF + (uint32_t)(o*256 + ((kc ^ (o&7)) << 4)), src + (size_t)i*16);
        }
        cpcommit();
    }

    // build hi/lo act images: row = channel c, col n = d*32+p, key (c>>1)&3
    #pragma unroll 1
    for (int it = 0; it < 6; it++){
        int idx = tid + it*512;
        int seg = idx & 7, d = (idx >> 3) % 3, c = idx / 24;
        float4 v = __ldg((const float4*)(pf + (((size_t)(b*128+c)*3+d)*NM + m0 + seg*4)));
        uint32_t off = (uint32_t)(c*ROWB + ((d*4 + ((seg>>1) ^ ((c>>1)&3))) << 4) + (seg&1)*8);
        uint2 hv = make_uint2(pk_hf(v.x, v.y), pk_hf(v.z, v.w));
        uint2 lv = make_uint2(pk_hf(v.x - hl(hv.x), v.y - hh(hv.x)),
                              pk_hf(v.z - hl(hv.y), v.w - hh(hv.y)));
        *(uint2*)(sm + off)       = hv;
        *(uint2*)(sm + IMG + off) = lv;
    }
    cpwait0();
    __syncthreads();

    float acc[2][3][4];
    const int bbase = b*128;

    #pragma unroll 1
    for (int l = 0; l < 4; l++){
        layer2p<2>(acc, Ws, sb, pq, mg*32, lane);
        __syncthreads();
        {
            const char* src = (const char*)g_W16[l+1];
            #pragma unroll
            for (int t = 0; t < 4; t++){
                int i = tid + t*512;
                int o = i >> 4, kc = i & 15;
                cp16(sm + WOFF + (uint32_t)(o*256 + ((kc ^ (o&7)) << 4)), src + (size_t)i*16);
            }
            cpcommit();
        }
        if      (l == 0) epi<0>(acc, sm, mg*32, pq, qr, cb, bbase);
        else if (l == 1) epi<1>(acc, sm, mg*32, pq, qr, cb, bbase);
        else if (l == 2) epi<2>(acc, sm, mg*32, pq, qr, cb, bbase);
        else             epi<1>(acc, sm, mg*32, pq, qr, cb, bbase);
        cpwait0();
        __syncthreads();
    }

    if (mg == 0){
        float facc[1][3][4];
        layer2p<1>(facc, Ws, sb, pq, 0, lane);
        if (lane < 8){
            const float sc = __ldg(scale + b);
            const int o2 = qr;
            #pragma unroll
            for (int d = 0; d < 3; d++){
                #pragma unroll
                for (int j = 0; j < 2; j++){
                    int p = pq*8 + cb + j;
                    float v = facc[0][d][j];
                    if (o2 == 0) v = v*sc + __ldg(center + b*3 + d);
                    out[((size_t)b*NM + m0 + p)*6 + o2*3 + d] = v;
                }
            }
        }
    }
}

// ---------------- fused setup: buildW (blk 0-39) | prep (40-47) | argmin (48-63) ----
__global__ void setup_k(const float* __restrict__ pc,
                        const float* __restrict__ z_pos, const float* __restrict__ z_dir,
                        const float* __restrict__ z_scalar, const float* __restrict__ gfeat,
                        const float* __restrict__ center, const float* __restrict__ scale,
                        const float* __restrict__ W1x, const float* __restrict__ W1xd,
                        const float* __restrict__ W1x_s, const float* __restrict__ W2x,
                        const float* __restrict__ W2xd, const float* __restrict__ W3x,
                        const float* __restrict__ W1g, const float* __restrict__ W1g_d,
                        const float* __restrict__ W1g_s, const float* __restrict__ W2g,
                        const float* __restrict__ W2g_d, const float* __restrict__ Wg_vs,
                        float* __restrict__ out)
{
    const int blk = blockIdx.x;
    const int tid = threadIdx.x;

    if (blk < 40){
        // ---- weight fp16 images ----
        const int m = blk >> 3, sub = blk & 7;
        #pragma unroll
        for (int t = 0; t < 8; t++){
            int i = sub*2048 + tid + t*256;
            int o = i >> 7, k = i & 127;
            float w = (m==0) ? W1x[o*136+k] : (m==1) ? W1xd[o*128+k] : (m==2) ? W2x[o*128+k]
                    : (m==3) ? W2xd[o*128+k] : ((o<2) ? W3x[o*128+k] : 0.0f);
            g_W16[m][i] = __float2half_rn(w);
        }
        return;
    }

    if (blk < 48){
        // ---- prep: bias/s2v + gripper branch (256 threads, 128 active per region) ----
        __shared__ float vg[136*3], bq[128*3], bhm[128*3], nh[128], zs[8*3];
        const int b = blk - 40, o = tid;
        if (o < 24){
            int r = o/3, d = o%3;
            zs[r*3+d] = (r < 2) ? (z_pos[(b*2+r)*3+d] - center[b*3+d]) / scale[b] : z_dir[(b*6+(r-2))*3+d];
        }
        __syncthreads();
        if (o < 128){
            g_s2v1[b*128+o] = W1x_s[o*2]*z_scalar[b*2] + W1x_s[o*2+1]*z_scalar[b*2+1];
            #pragma unroll
            for (int d = 0; d < 3; d++){
                float s = 0.0f;
                #pragma unroll
                for (int k = 0; k < 8; k++) s += W1x[o*136 + 128 + k] * zs[k*3+d];
                g_bias1[(b*128+o)*3+d] = s;
            }
        }
        for (int i = o; i < 408; i += 256){
            int c = i/3, d = i%3;
            vg[i] = (c < 128) ? gfeat[(b*128+c)*3+d] : zs[(c-128)*3+d];
        }
        __syncthreads();
        float q[3], dv[3];
        if (o < 128){
            #pragma unroll
            for (int d = 0; d < 3; d++){ float s=0; for (int c=0;c<136;c++) s += W1g[o*136+c]*vg[c*3+d]; q[d]=s; }
            float sg = W1g_s[o*2]*z_scalar[b*2] + W1g_s[o*2+1]*z_scalar[b*2+1];
            float g = 1.0f + sg/(sqrtf(q[0]*q[0]+q[1]*q[1]+q[2]*q[2])+EPSN);
            q[0]*=g; q[1]*=g; q[2]*=g;
            bq[o*3]=q[0]; bq[o*3+1]=q[1]; bq[o*3+2]=q[2];
        }
        __syncthreads();
        if (o < 128){
            #pragma unroll
            for (int d = 0; d < 3; d++){ float s=0; for (int c=0;c<128;c++) s += W1g_d[o*128+c]*bq[c*3+d]; dv[d]=s; }
            float inv = 1.0f/(sqrtf(dv[0]*dv[0]+dv[1]*dv[1]+dv[2]*dv[2]) + EPSN);
            float mf = fminf((q[0]*dv[0]+q[1]*dv[1]+q[2]*dv[2])*inv, 0.0f)*inv;
            q[0]-=mf*dv[0]; q[1]-=mf*dv[1]; q[2]-=mf*dv[2];
            bhm[o*3]=q[0]; bhm[o*3+1]=q[1]; bhm[o*3+2]=q[2];
        }
        __syncthreads();
        if (o < 128){
            #pragma unroll
            for (int d = 0; d < 3; d++){ float s=0; for (int c=0;c<128;c++) s += W2g[o*128+c]*bhm[c*3+d]; q[d]=s; }
            bq[o*3]=q[0]; bq[o*3+1]=q[1]; bq[o*3+2]=q[2];
        }
        __syncthreads();
        if (o < 128){
            #pragma unroll
            for (int d = 0; d < 3; d++){ float s=0; for (int c=0;c<128;c++) s += W2g_d[o*128+c]*bq[c*3+d]; dv[d]=s; }
            float inv = 1.0f/(sqrtf(dv[0]*dv[0]+dv[1]*dv[1]+dv[2]*dv[2]) + EPSN);
            float mf = fminf((q[0]*dv[0]+q[1]*dv[1]+q[2]*dv[2])*inv, 0.0f)*inv;
            q[0]-=mf*dv[0]; q[1]-=mf*dv[1]; q[2]-=mf*dv[2];
            nh[o] = sqrtf(q[0]*q[0]+q[1]*q[1]+q[2]*q[2]);
        }
        __syncthreads();
        if (o < 2){
            float s = 0; for (int c = 0; c < 128; c++) s += Wg_vs[o*128+c]*nh[c];
            float gr = 1.0f/(1.0f+expf(-s));
            g_grip[b*2+o] = gr;
            out[GRIP_OFF + b*2+o] = gr;
        }
        return;
    }

    // ---- argmin (blocks 48-63) ----
    {
        __shared__ float sv[256]; __shared__ int si[256];
        const int be = blk - 48, b = be >> 1;
        const float inv = 1.0f / scale[b];
        const float zx = (z_pos[be*3+0] - center[b*3+0]) * inv;
        const float zy = (z_pos[be*3+1] - center[b*3+1]) * inv;
        const float zz = (z_pos[be*3+2] - center[b*3+2]) * inv;
        const float* p = pc + (size_t)b*NM*3;
        float best = 3.4e38f; int bi = 0;
        #pragma unroll 4
        for (int m = tid; m < NM; m += 256){
            float dx=zx-p[m*3], dy=zy-p[m*3+1], dz=zz-p[m*3+2];
            float d = sqrtf(dx*dx+dy*dy+dz*dz);
            if (d < best){ best = d; bi = m; }
        }
        sv[tid]=best; si[tid]=bi;
        __syncthreads();
        for (int s = 128; s > 0; s >>= 1){
            if (tid < s){
                float ov = sv[tid+s]; int oi = si[tid+s];
                if (ov < sv[tid] || (ov == sv[tid] && oi < si[tid])){
                    sv[tid]=ov; si[tid]=oi;
                }
            }
            __syncthreads();
        }
        if (tid == 0) g_closest[be] = si[0];
    }
}

__global__ void assemble_k(float* __restrict__ out)
{
    const int t = threadIdx.x;
    if (t < 112){
        int b = t/14, j = t%14, e = j/7, r = j%7;
        float v;
        if (r == 0) v = g_grip[b*2+e];
        else { int m = g_closest[b*2+e]; v = out[((size_t)b*NM+m)*6 + (r-1)]; }
        out[AC_OFF + t] = v;
    }
}

// ---------------- launch ----------------
extern "C" void kernel_launch(void* const* d_in, const int* in_sizes, int n_in,
                              void* d_out, int out_size)
{
    const float* pc        = (const float*)d_in[0];
    const float* z_pos     = (const float*)d_in[1];
    const float* z_dir     = (const float*)d_in[2];
    const float* z_scalar  = (const float*)d_in[3];
    const float* point_feat= (const float*)d_in[4];
    const float* gfeat     = (const float*)d_in[5];
    const float* center    = (const float*)d_in[6];
    const float* scale     = (const float*)d_in[7];
    const float* W1x       = (const float*)d_in[8];
    const float* W1x_d     = (const float*)d_in[9];
    const float* W1x_s     = (const float*)d_in[10];
    const float* W2x       = (const float*)d_in[11];
    const float* W2x_d     = (const float*)d_in[12];
    const float* W3x       = (const float*)d_in[13];
    const float* W1g       = (const float*)d_in[14];
    const float* W1g_d     = (const float*)d_in[15];
    const float* W1g_s     = (const float*)d_in[16];
    const float* W2g       = (const float*)d_in[17];
    const float* W2g_d     = (const float*)d_in[18];
    const float* Wg_vs     = (const float*)d_in[19];
    float* out = (float*)d_out;

    cudaFuncSetAttribute(main_mma, cudaFuncAttributeMaxDynamicSharedMemorySize, SMEM_TOTAL);

    setup_k<<<64, 256>>>(pc, z_pos, z_dir, z_scalar, gfeat, center, scale,
                         W1x, W1x_d, W1x_s, W2x, W2x_d, W3x,
                         W1g, W1g_d, W1g_s, W2g, W2g_d, Wg_vs, out);
    main_mma<<<dim3(NM/TSP, NB), 512, SMEM_TOTAL>>>(point_feat, scale, center, out);
    assemble_k<<<1, 128>>>(out);
}